// round 13
// baseline (speedup 1.0000x reference)
#include <cuda_runtime.h>
#include <cuda_bf16.h>
#include <cuda_fp16.h>
#include <math.h>
#include <stdint.h>
#include <stddef.h>

#define S_LEN  2048
#define BATCH  2
#define DMODEL 1024
#define NHEADS 16
#define HDIM   64
#define M_ROWS 4096
#define NBH    (BATCH * NHEADS)
#define SCL    0.18033688011112042f   // 0.125 * log2(e)
#define LOG2E  1.4426950408889634f

typedef __nv_bfloat16 bf16;

#if defined(__CUDA_ARCH__) && (defined(__CUDA_ARCH_SPECIFIC__) || \
    defined(__CUDA_ARCH_FEAT_SM103_ALL) || defined(__CUDA_ARCH_FEAT_SM100_ALL))
#define TC_OK 1
#else
#define TC_OK 0
#endif

// ------------------------------ scratch (tile-packed) ----------------------
__device__ __align__(128) bf16 g_srchi[M_ROWS * DMODEL];
__device__ __align__(128) bf16 g_srclo[M_ROWS * DMODEL];
__device__ __align__(128) bf16 g_atthi[M_ROWS * DMODEL];
__device__ __align__(128) bf16 g_attlo[M_ROWS * DMODEL];
__device__ __align__(128) bf16 g_whi[4][DMODEL * DMODEL];
__device__ __align__(128) bf16 g_wlo[4][DMODEL * DMODEL];
__device__ __align__(128) bf16 g_qhi[NBH * S_LEN * HDIM];
__device__ __align__(128) bf16 g_qlo[NBH * S_LEN * HDIM];
__device__ __align__(128) bf16 g_khi[NBH * S_LEN * HDIM];
__device__ __align__(128) bf16 g_klo[NBH * S_LEN * HDIM];
__device__ __align__(128) bf16 g_vthi[NBH * HDIM * S_LEN];
__device__ __align__(128) bf16 g_vtlo[NBH * HDIM * S_LEN];
__device__ float  g_v[M_ROWS * DMODEL];
__device__ __half g_bias2h[S_LEN * S_LEN];   // bias * log2(e), fp16

// ------------------------------ helpers ------------------------------------
__device__ __forceinline__ uint32_t smem_u32(const void* p) {
    uint32_t a;
    asm("{ .reg .u64 t; cvta.to.shared.u64 t, %1; cvt.u32.u64 %0, t; }"
        : "=r"(a) : "l"(p));
    return a;
}
__device__ __forceinline__ float ex2_fast(float x) {
    float r;
    asm("ex2.approx.ftz.f32 %0, %1;" : "=f"(r) : "f"(x));
    return r;
}
__device__ __forceinline__ uint32_t swz(uint32_t off) {
    return off ^ ((off >> 3) & 0x70);
}
__device__ __forceinline__ void bulkcp(uint32_t dst, const void* src,
                                       uint32_t bytes, uint32_t mbar) {
    asm volatile(
        "cp.async.bulk.shared::cluster.global.mbarrier::complete_tx::bytes "
        "[%0], [%1], %2, [%3];"
        :: "r"(dst), "l"(src), "r"(bytes), "r"(mbar) : "memory");
}
__device__ __forceinline__ void bulkcp_mc(uint32_t dst, const void* src,
                                          uint32_t bytes, uint32_t mbar,
                                          uint16_t mask) {
    asm volatile(
        "cp.async.bulk.shared::cluster.global.mbarrier::complete_tx::bytes"
        ".multicast::cluster [%0], [%1], %2, [%3], %4;"
        :: "r"(dst), "l"(src), "r"(bytes), "r"(mbar), "h"(mask) : "memory");
}
__device__ __forceinline__ uint32_t cta_rank() {
    uint32_t r;
    asm("mov.u32 %0, %%cluster_ctarank;" : "=r"(r));
    return r;
}
#define MBARRIER_INIT(mb, c) \
    asm volatile("mbarrier.init.shared.b64 [%0], %1;" :: "r"((uint32_t)(mb)), "r"((uint32_t)(c)) : "memory")
#define MBARRIER_EXPECT_TX(mb, tx) \
    asm volatile("mbarrier.arrive.expect_tx.shared.b64 _, [%0], %1;" \
                 :: "r"((uint32_t)(mb)), "r"((uint32_t)(tx)) : "memory")
#define MBARRIER_ARRIVE(mb) \
    asm volatile("mbarrier.arrive.shared.b64 _, [%0];" :: "r"((uint32_t)(mb)) : "memory")
#define MBARRIER_ARRIVE_PEER(mb, peer) \
    asm volatile("{\n\t.reg .b32 ra;\n\tmapa.shared::cluster.u32 ra, %0, %1;\n\t" \
        "mbarrier.arrive.shared::cluster.b64 _, [ra];\n\t}" \
        :: "r"((uint32_t)(mb)), "r"((uint32_t)(peer)) : "memory")
#define MBAR_WAIT(mb, par) do {                                                  \
    uint32_t _m = (uint32_t)(mb); uint32_t _p = (uint32_t)(par); uint32_t _d;    \
    asm volatile("{\n\t.reg .pred p;\n\t"                                        \
        "mbarrier.try_wait.parity.acquire.cta.shared::cta.b64 p, [%1], %2;\n\t"  \
        "selp.b32 %0, 1, 0, p;\n\t}" : "=r"(_d) : "r"(_m), "r"(_p) : "memory");  \
    if (!_d) {                                                                   \
        asm volatile("{\n\t.reg .pred P1;\n\tWL_%=:\n\t"                         \
            "mbarrier.try_wait.parity.acquire.cta.shared::cta.b64 P1, [%0], %1, 0x989680;\n\t" \
            "@P1 bra.uni WD_%=;\n\tbra.uni WL_%=;\n\tWD_%=:\n\t}"                \
            :: "r"(_m), "r"(_p) : "memory");                                     \
    } } while (0)
#define CLUSTER_SYNC() do { \
    asm volatile("barrier.cluster.arrive.aligned;" ::: "memory"); \
    asm volatile("barrier.cluster.wait.aligned;" ::: "memory"); } while (0)

// ---- packed-layout index helpers ----
__device__ __forceinline__ size_t act_off(int m, int k) {
    uint32_t byte = swz((uint32_t)((((m & 127) * 8) + ((k & 63) >> 3)) * 16)) + (k & 7) * 2;
    return ((size_t)((m >> 7) * 16 + (k >> 6))) * 8192 + (byte >> 1);
}
__device__ __forceinline__ size_t w_off(int n, int k) {
    uint32_t byte = (uint32_t)(((n >> 7) & 1) * 16384)
                  + swz((uint32_t)((((n & 127) * 8) + ((k & 63) >> 3)) * 16)) + (k & 7) * 2;
    return ((size_t)((n >> 8) * 16 + (k >> 6))) * 16384 + (byte >> 1);
}
__device__ __forceinline__ size_t qk_off(int bh, int s, int d) {
    uint32_t byte = swz((uint32_t)((((s & 127) * 8) + (d >> 3)) * 16)) + (d & 7) * 2;
    return ((size_t)(bh * 16 + (s >> 7))) * 8192 + (byte >> 1);
}
__device__ __forceinline__ size_t v_off(int bh, int s, int d) {
    uint32_t byte = (uint32_t)(((s & 127) >> 6) * 8192)
                  + swz((uint32_t)((d * 8 + ((s & 63) >> 3)) * 16)) + (s & 7) * 2;
    return ((size_t)(bh * 16 + (s >> 7))) * 8192 + (byte >> 1);
}

#if TC_OK
#define TCGEN05_ALLOC(sa, n) \
    asm volatile("tcgen05.alloc.cta_group::1.sync.aligned.shared::cta.b32 [%0], %1;" \
                 :: "r"((uint32_t)(sa)), "r"((uint32_t)(n)) : "memory")
#define TCGEN05_DEALLOC(t, n) \
    asm volatile("tcgen05.dealloc.cta_group::1.sync.aligned.b32 %0, %1;" :: "r"(t), "r"((uint32_t)(n)))
#define TCGEN05_RELINQ() \
    asm volatile("tcgen05.relinquish_alloc_permit.cta_group::1.sync.aligned;")
#define TCGEN05_COMMIT(mb) \
    asm volatile("tcgen05.commit.cta_group::1.mbarrier::arrive::one.shared::cluster.b64 [%0];" \
                 :: "r"((uint32_t)(mb)) : "memory")
#define TCGEN05_FENCE_AFTER()  asm volatile("tcgen05.fence::after_thread_sync;" ::: "memory")
#define TCGEN05_FENCE_BEFORE() asm volatile("tcgen05.fence::before_thread_sync;" ::: "memory")
#define TCGEN05_WAIT_LD()      asm volatile("tcgen05.wait::ld.sync.aligned;" ::: "memory")
#define TCGEN05_LD_X32(r, ta) \
    asm volatile("tcgen05.ld.sync.aligned.32x32b.x32.b32 " \
        "{%0,%1,%2,%3,%4,%5,%6,%7,%8,%9,%10,%11,%12,%13,%14,%15," \
        "%16,%17,%18,%19,%20,%21,%22,%23,%24,%25,%26,%27,%28,%29,%30,%31}, [%32];" \
        : "=r"((r)[0]),"=r"((r)[1]),"=r"((r)[2]),"=r"((r)[3]),"=r"((r)[4]),"=r"((r)[5]),"=r"((r)[6]),"=r"((r)[7]), \
          "=r"((r)[8]),"=r"((r)[9]),"=r"((r)[10]),"=r"((r)[11]),"=r"((r)[12]),"=r"((r)[13]),"=r"((r)[14]),"=r"((r)[15]), \
          "=r"((r)[16]),"=r"((r)[17]),"=r"((r)[18]),"=r"((r)[19]),"=r"((r)[20]),"=r"((r)[21]),"=r"((r)[22]),"=r"((r)[23]), \
          "=r"((r)[24]),"=r"((r)[25]),"=r"((r)[26]),"=r"((r)[27]),"=r"((r)[28]),"=r"((r)[29]),"=r"((r)[30]),"=r"((r)[31]) \
        : "r"(ta))

static __device__ __forceinline__ uint64_t make_desc_sw128(uint32_t base) {
    const uint64_t B = (uint64_t(2) << 61) | (uint64_t(1) << 46)
                     | (uint64_t(64) << 32) | (uint64_t(1) << 16);
    return B | ((uint64_t)(base >> 4) & 0x3FFF);
}
__device__ __forceinline__ void mma_f16_ss(uint32_t d, uint64_t a, uint64_t b,
                                           uint32_t idesc, uint32_t en) {
    asm volatile("{\n\t.reg .pred p;\n\tsetp.ne.u32 p, %5, 0;\n\t"
        "tcgen05.mma.cta_group::1.kind::f16 [%0], %1, %2, %3, {%4,%4,%4,%4}, p;\n\t}"
        :: "r"(d), "l"(a), "l"(b), "r"(idesc), "r"(0u), "r"(en) : "memory");
}
#endif // TC_OK

// ------------------------------ prep kernels -------------------------------
__global__ void split_kernel(const float* __restrict__ in,
                             bf16* __restrict__ hi, bf16* __restrict__ lo)
{
    int idx = blockIdx.x * blockDim.x + threadIdx.x;
    int m = idx >> 7, k = (idx & 127) * 8;
    float4 a = *(const float4*)&in[(size_t)m * DMODEL + k];
    float4 b = *(const float4*)&in[(size_t)m * DMODEL + k + 4];
    float f[8] = {a.x, a.y, a.z, a.w, b.x, b.y, b.z, b.w};
    uint32_t H[4], L[4];
#pragma unroll
    for (int e = 0; e < 4; e++) {
        uint32_t hh;
        asm("cvt.rn.bf16x2.f32 %0, %1, %2;" : "=r"(hh) : "f"(f[2*e+1]), "f"(f[2*e]));
        __nv_bfloat162 hv = *(__nv_bfloat162*)&hh;
        float r0 = f[2*e]   - __bfloat162float(hv.x);
        float r1 = f[2*e+1] - __bfloat162float(hv.y);
        uint32_t ll;
        asm("cvt.rn.bf16x2.f32 %0, %1, %2;" : "=r"(ll) : "f"(r1), "f"(r0));
        H[e] = hh; L[e] = ll;
    }
    size_t off = act_off(m, k);
    *(uint4*)&hi[off] = make_uint4(H[0], H[1], H[2], H[3]);
    *(uint4*)&lo[off] = make_uint4(L[0], L[1], L[2], L[3]);
}

__global__ void bscale_kernel(const float* __restrict__ in)
{
    int i = blockIdx.x * blockDim.x + threadIdx.x;
    float4 x = ((const float4*)in)[i];
    __half2 h0 = __floats2half2_rn(x.x * LOG2E, x.y * LOG2E);
    __half2 h1 = __floats2half2_rn(x.z * LOG2E, x.w * LOG2E);
    uint2 pk = make_uint2(*(uint32_t*)&h0, *(uint32_t*)&h1);
    ((uint2*)g_bias2h)[i] = pk;
}

__global__ void wprep_kernel(const float* __restrict__ w0, const float* __restrict__ w1,
                             const float* __restrict__ w2, const float* __restrict__ w3)
{
    __shared__ float t[32][33];
    const float* W = (blockIdx.z == 0) ? w0 : (blockIdx.z == 1) ? w1
                   : (blockIdx.z == 2) ? w2 : w3;
    bf16* Whi = g_whi[blockIdx.z];
    bf16* Wlo = g_wlo[blockIdx.z];
    const int n0 = blockIdx.x * 32, k0 = blockIdx.y * 32;
    const int tx = threadIdx.x, ty = threadIdx.y;
#pragma unroll
    for (int i = 0; i < 4; i++)
        t[ty + i * 8][tx] = W[(size_t)(k0 + ty + i * 8) * DMODEL + n0 + tx];
    __syncthreads();
#pragma unroll
    for (int i = 0; i < 4; i++) {
        const int n = n0 + ty + i * 8, k = k0 + tx;
        float v = t[tx][ty + i * 8];
        bf16 h = __float2bfloat16_rn(v);
        size_t o = w_off(n, k);
        Whi[o] = h;
        Wlo[o] = __float2bfloat16_rn(v - __bfloat162float(h));
    }
}

__global__ __launch_bounds__(256)
void vtrans_kernel()
{
    __shared__ float t[64][65];
    const int bh = blockIdx.y, b = bh >> 4, h = bh & 15;
    const int s0 = blockIdx.x * 128;
    const int tid = threadIdx.x;
    for (int half = 0; half < 2; half++) {
        __syncthreads();
#pragma unroll
        for (int p = 0; p < 16; p++) {
            const int idx = tid + p * 256;
            const int d = idx & 63, sl = idx >> 6;
            t[d][sl] = g_v[(size_t)((s0 + half * 64 + sl) * 2 + b) * DMODEL + h * 64 + d];
        }
        __syncthreads();
#pragma unroll
        for (int p = 0; p < 8; p++) {
            const int idx = tid + p * 256;
            const int sp2 = idx & 31, d = idx >> 5;
            const int s = s0 + half * 64 + sp2 * 2;
            float v0 = t[d][sp2 * 2], v1 = t[d][sp2 * 2 + 1];
            __nv_bfloat162 H, L;
            H.x = __float2bfloat16_rn(v0);
            H.y = __float2bfloat16_rn(v1);
            L.x = __float2bfloat16_rn(v0 - __bfloat162float(H.x));
            L.y = __float2bfloat16_rn(v1 - __bfloat162float(H.y));
            const size_t o = v_off(bh, s, d);
            *(__nv_bfloat162*)&g_vthi[o] = H;
            *(__nv_bfloat162*)&g_vtlo[o] = L;
        }
    }
}

// --------------- tcgen05 GEMM (128x256, 2-stage, bulk-copy) ----------------
#define GTHREADS 512
#define GT_M 128
#define GT_N 256
#define GT_K 64
#define NCHUNK (DMODEL / GT_K)
#define OFF_AH 0
#define OFF_AL 16384
#define OFF_BH 32768
#define OFF_BL 65536
#define STAGE_B 98304
#define GEMM_SMEM (2 * STAGE_B + 1024)
#define GT_IDESC ((1u<<4)|(1u<<7)|(1u<<10)|(16u<<17)|(8u<<24))

__device__ __forceinline__ void gemm_core(
    const bf16* __restrict__ Ah, const bf16* __restrict__ Al,
    const bf16* __restrict__ Bh, const bf16* __restrict__ Bl,
    const float* __restrict__ bias, float* __restrict__ outf,
    bf16* __restrict__ outhi, bf16* __restrict__ outlo, int mode,
    char* dyn, uint32_t* s_tmem_p, uint64_t* s_mbar)
{
#if TC_OK
    const int tid = threadIdx.x, wid = tid >> 5, lid = tid & 31;
    const int n0 = blockIdx.x * GT_N, m0 = blockIdx.y * GT_M;
    const int mt = m0 >> 7, nt = n0 >> 8;

    uint32_t base = smem_u32(dyn);
    base = (base + 1023u) & ~1023u;
    const uint32_t full[2] = { smem_u32(&s_mbar[0]), smem_u32(&s_mbar[1]) };
    const uint32_t mmb[2]  = { smem_u32(&s_mbar[2]), smem_u32(&s_mbar[3]) };

    if (wid == 0) { TCGEN05_ALLOC(smem_u32(s_tmem_p), 256); TCGEN05_RELINQ(); }
    if (tid == 0) {
        MBARRIER_INIT(full[0], 1); MBARRIER_INIT(full[1], 1);
        MBARRIER_INIT(mmb[0], 1);  MBARRIER_INIT(mmb[1], 1);
    }
    __syncthreads();
    const uint32_t tmem = *s_tmem_p;

    if (tid == 0) {
#pragma unroll
        for (int c0 = 0; c0 < 2; c0++) {
            const uint32_t ss = base + c0 * STAGE_B;
            MBARRIER_EXPECT_TX(full[c0], (uint32_t)STAGE_B);
            bulkcp(ss + OFF_AH, Ah + (size_t)(mt * 16 + c0) * 8192,  16384, full[c0]);
            bulkcp(ss + OFF_AL, Al + (size_t)(mt * 16 + c0) * 8192,  16384, full[c0]);
            bulkcp(ss + OFF_BH, Bh + (size_t)(nt * 16 + c0) * 16384, 32768, full[c0]);
            bulkcp(ss + OFF_BL, Bl + (size_t)(nt * 16 + c0) * 16384, 32768, full[c0]);
        }
        int phF[2] = {0, 0}, phM[2] = {0, 0};
        for (int c = 0; c < NCHUNK; c++) {
            const int s = c & 1;
            const uint32_t ss = base + s * STAGE_B;
            MBAR_WAIT(full[s], phF[s]); phF[s] ^= 1;
            const uint64_t dAh = make_desc_sw128(ss + OFF_AH);
            const uint64_t dAl = make_desc_sw128(ss + OFF_AL);
#pragma unroll
            for (int sub = 0; sub < 2; sub++) {
                const uint64_t dBh = make_desc_sw128(ss + OFF_BH + sub * 16384);
                const uint64_t dBl = make_desc_sw128(ss + OFF_BL + sub * 16384);
                const uint32_t dst = tmem + sub * 128;
#pragma unroll
                for (int ks = 0; ks < 4; ks++)
                    mma_f16_ss(dst, dAh + ks * 2, dBh + ks * 2, GT_IDESC,
                               (c == 0 && ks == 0) ? 0u : 1u);
#pragma unroll
                for (int ks = 0; ks < 4; ks++)
                    mma_f16_ss(dst, dAh + ks * 2, dBl + ks * 2, GT_IDESC, 1u);
#pragma unroll
                for (int ks = 0; ks < 4; ks++)
                    mma_f16_ss(dst, dAl + ks * 2, dBh + ks * 2, GT_IDESC, 1u);
            }
            TCGEN05_COMMIT(mmb[s]);
            if (c + 2 < NCHUNK) {
                MBAR_WAIT(mmb[s], phM[s]); phM[s] ^= 1;
                MBARRIER_EXPECT_TX(full[s], (uint32_t)STAGE_B);
                bulkcp(ss + OFF_AH, Ah + (size_t)(mt * 16 + c + 2) * 8192,  16384, full[s]);
                bulkcp(ss + OFF_AL, Al + (size_t)(mt * 16 + c + 2) * 8192,  16384, full[s]);
                bulkcp(ss + OFF_BH, Bh + (size_t)(nt * 16 + c + 2) * 16384, 32768, full[s]);
                bulkcp(ss + OFF_BL, Bl + (size_t)(nt * 16 + c + 2) * 16384, 32768, full[s]);
            }
        }
        MBAR_WAIT(mmb[0], phM[0]);
        MBAR_WAIT(mmb[1], phM[1]);
    }
    __syncthreads();
    TCGEN05_FENCE_AFTER();

    {
        const int m = m0 + (wid & 3) * 32 + lid;
        const int s = m >> 1, b = m & 1;
#pragma unroll
        for (int gg = 0; gg < 2; gg++) {
            const int g = (wid >> 2) + gg * 4;
            uint32_t r[32];
            TCGEN05_LD_X32(r, tmem + g * 32);
            TCGEN05_WAIT_LD();
            const int cb = n0 + g * 32;
            if (mode == 0) {
#pragma unroll
                for (int q = 0; q < 8; q++) {
                    float4 v;
                    v.x = __uint_as_float(r[q * 4 + 0]) + bias[cb + q * 4 + 0];
                    v.y = __uint_as_float(r[q * 4 + 1]) + bias[cb + q * 4 + 1];
                    v.z = __uint_as_float(r[q * 4 + 2]) + bias[cb + q * 4 + 2];
                    v.w = __uint_as_float(r[q * 4 + 3]) + bias[cb + q * 4 + 3];
                    *(float4*)&outf[(size_t)m * DMODEL + cb + q * 4] = v;
                }
            } else {
                const int h = cb >> 6;
                const int bh = b * NHEADS + h;
#pragma unroll
                for (int q = 0; q < 16; q++) {
                    const int co = cb + q * 2;
                    float v0 = __uint_as_float(r[q * 2 + 0]) + bias[co + 0];
                    float v1 = __uint_as_float(r[q * 2 + 1]) + bias[co + 1];
                    __nv_bfloat162 H, L;
                    H.x = __float2bfloat16_rn(v0);
                    H.y = __float2bfloat16_rn(v1);
                    L.x = __float2bfloat16_rn(v0 - __bfloat162float(H.x));
                    L.y = __float2bfloat16_rn(v1 - __bfloat162float(H.y));
                    const size_t o = qk_off(bh, s, co & 63);
                    *(__nv_bfloat162*)&outhi[o] = H;
                    *(__nv_bfloat162*)&outlo[o] = L;
                }
            }
        }
        TCGEN05_FENCE_BEFORE();
    }
    __syncthreads();
    if (wid == 0) TCGEN05_DEALLOC(tmem, 256);
#else
    const int tid = threadIdx.x;
    const int n0 = blockIdx.x * GT_N, m0 = blockIdx.y * GT_M;
    for (int idx = tid; idx < GT_M * GT_N; idx += GTHREADS) {
        const int m = m0 + idx / GT_N, n = n0 + idx % GT_N;
        float sacc = bias[n];
        for (int k = 0; k < DMODEL; k++) {
            float a = __bfloat162float(Ah[act_off(m, k)]) +
                      __bfloat162float(Al[act_off(m, k)]);
            float bb = __bfloat162float(Bh[w_off(n, k)]) +
                       __bfloat162float(Bl[w_off(n, k)]);
            sacc = fmaf(a, bb, sacc);
        }
        if (mode == 0) outf[(size_t)m * DMODEL + n] = sacc;
        else {
            const int s = m >> 1, b = m & 1, h = n >> 6, d = n & 63;
            const size_t o = qk_off(b * NHEADS + h, s, d);
            bf16 hv = __float2bfloat16_rn(sacc);
            outhi[o] = hv;
            outlo[o] = __float2bfloat16_rn(sacc - __bfloat162float(hv));
        }
    }
#endif
}

__global__ __launch_bounds__(GTHREADS, 1)
void qkv_kernel(const float* __restrict__ bq, const float* __restrict__ bk,
                const float* __restrict__ bv)
{
    extern __shared__ char dyn[];
    __shared__ uint32_t s_tmem;
    __shared__ uint64_t s_mbar[4];
    const int z = blockIdx.z;
    if (z == 0)
        gemm_core(g_srchi, g_srclo, g_whi[0], g_wlo[0], bq, nullptr,
                  g_qhi, g_qlo, 1, dyn, &s_tmem, s_mbar);
    else if (z == 1)
        gemm_core(g_srchi, g_srclo, g_whi[1], g_wlo[1], bk, nullptr,
                  g_khi, g_klo, 1, dyn, &s_tmem, s_mbar);
    else
        gemm_core(g_srchi, g_srclo, g_whi[2], g_wlo[2], bv, g_v,
                  nullptr, nullptr, 0, dyn, &s_tmem, s_mbar);
}

__global__ __launch_bounds__(GTHREADS, 1)
void outproj_kernel(const float* __restrict__ bo, float* __restrict__ out)
{
    extern __shared__ char dyn[];
    __shared__ uint32_t s_tmem;
    __shared__ uint64_t s_mbar[4];
    gemm_core(g_atthi, g_attlo, g_whi[3], g_wlo[3], bo, out,
              nullptr, nullptr, 0, dyn, &s_tmem, s_mbar);
}

// --------------------------- tcgen05 attention (cluster-2) -----------------
#define AQ_H  0
#define AQ_L  16384
#define AK(s) (32768 + (s) * 32768)
#define AV(s) (98304 + (s) * 32768)
#define AP    163840
#define ATTN_DYN (229376 + 1024)
#define IDESC_S  ((1u<<4)|(1u<<7)|(1u<<10)|(16u<<17)|(8u<<24))
#define IDESC_PV ((1u<<4)|(1u<<7)|(1u<<10)|(8u<<17)|(8u<<24))

__global__ __launch_bounds__(256, 1) __cluster_dims__(2, 1, 1)
void attn_tc_kernel()
{
#if TC_OK
    extern __shared__ char dyn[];
    __shared__ uint32_t s_tmem;
    __shared__ uint64_t s_mb[6];   // mbS, mbP, fullKV0, fullKV1, ready0, ready1
    __shared__ float sm_red[2][128];

    const int tid = threadIdx.x, wid = tid >> 5, lid = tid & 31;
    const int g = wid >> 2;
    const int sp = wid & 3;
    const int row = sp * 32 + lid;
    const int bh = blockIdx.y;
    const int b = bh >> 4, h = bh & 15;
    const int q0 = blockIdx.x * 128;
    const uint32_t rank = cta_rank();
    const uint32_t peer = 1 - rank;

    uint32_t base = smem_u32(dyn);
    base = (base + 1023u) & ~1023u;
    char* smp = dyn + (ptrdiff_t)(base - smem_u32(dyn));
    const uint32_t mbS = smem_u32(&s_mb[0]), mbP = smem_u32(&s_mb[1]);
    const uint32_t fullKV[2] = { smem_u32(&s_mb[2]), smem_u32(&s_mb[3]) };
    const uint32_t ready[2]  = { smem_u32(&s_mb[4]), smem_u32(&s_mb[5]) };

    if (wid == 0) { TCGEN05_ALLOC(smem_u32(&s_tmem), 512); TCGEN05_RELINQ(); }
    if (tid == 0) {
        MBARRIER_INIT(mbS, 1); MBARRIER_INIT(mbP, 1);
        MBARRIER_INIT(fullKV[0], 1); MBARRIER_INIT(fullKV[1], 1);
        MBARRIER_INIT(ready[0], 2);  MBARRIER_INIT(ready[1], 2);
    }
    __syncthreads();
    CLUSTER_SYNC();   // all barriers visible cluster-wide before any multicast
    const uint32_t tmem = s_tmem;

    int phF0 = 0, phF1 = 0;
    // ---- prologue: Q (local) + K0/V0 (rank-split multicast), then S(0) ----
    if (tid == 0) {
        MBARRIER_EXPECT_TX(fullKV[0], 6 * 16384);
        bulkcp(base + AQ_H, g_qhi + (size_t)(bh * 16 + (q0 >> 7)) * 8192, 16384, fullKV[0]);
        bulkcp(base + AQ_L, g_qlo + (size_t)(bh * 16 + (q0 >> 7)) * 8192, 16384, fullKV[0]);
        if (rank == 0) {
            bulkcp_mc(base + AK(0),          g_khi  + (size_t)(bh * 16) * 8192, 16384, fullKV[0], 3);
            bulkcp_mc(base + AK(0) + 16384,  g_klo  + (size_t)(bh * 16) * 8192, 16384, fullKV[0], 3);
        } else {
            bulkcp_mc(base + AV(0),          g_vthi + (size_t)(bh * 16) * 8192, 16384, fullKV[0], 3);
            bulkcp_mc(base + AV(0) + 16384,  g_vtlo + (size_t)(bh * 16) * 8192, 16384, fullKV[0], 3);
        }
        MBAR_WAIT(fullKV[0], 0); phF0 = 1;
        const uint64_t dQh = make_desc_sw128(base + AQ_H);
        const uint64_t dQl = make_desc_sw128(base + AQ_L);
        const uint64_t dKh = make_desc_sw128(base + AK(0));
        const uint64_t dKl = make_desc_sw128(base + AK(0) + 16384);
#pragma unroll
        for (int ks = 0; ks < 4; ks++) mma_f16_ss(tmem, dQh + ks*2, dKh + ks*2, IDESC_S, ks > 0);
#pragma unroll
        for (int ks = 0; ks < 4; ks++) mma_f16_ss(tmem, dQh + ks*2, dKl + ks*2, IDESC_S, 1);
#pragma unroll
        for (int ks = 0; ks < 4; ks++) mma_f16_ss(tmem, dQl + ks*2, dKh + ks*2, IDESC_S, 1);
        TCGEN05_COMMIT(mbS);
    }

    float l = 0.f;
    uint32_t phS = 0, phP = 0;
    int phR[2] = {0, 0};
    const __half* bp = g_bias2h + (size_t)(q0 + row) * S_LEN + g * 64;

    for (int t = 0; t < 16; t++) {
        const int k0 = t * 128;
        const int stg = t & 1;
        const int nst = (t + 1) & 1;

        // hoisted fp16 bias loads
        __half2 hb[32];
#pragma unroll
        for (int j4 = 0; j4 < 16; j4++)
            *(uint2*)&hb[j4 * 2] = *(const uint2*)&bp[k0 + j4 * 4];

        // S(t) ready; read it
        MBAR_WAIT(mbS, phS); phS ^= 1;
        TCGEN05_FENCE_AFTER();
        float sv[64];
        {
            uint32_t r32a[32], r32b[32];
            TCGEN05_LD_X32(r32a, tmem + stg * 128 + g * 64);
            TCGEN05_LD_X32(r32b, tmem + stg * 128 + g * 64 + 32);
            TCGEN05_WAIT_LD();
#pragma unroll
            for (int i = 0; i < 32; i++) sv[i] = __uint_as_float(r32a[i]);
#pragma unroll
            for (int i = 0; i < 32; i++) sv[32 + i] = __uint_as_float(r32b[i]);
            TCGEN05_FENCE_BEFORE();
        }

        // PV(t-1) done -> stage nst free locally; signal both CTAs' ready
        if (t > 0) {
            MBAR_WAIT(mbP, phP); phP ^= 1;
            TCGEN05_FENCE_AFTER();
            if (tid == 0 && t < 15) {
                MBARRIER_ARRIVE(ready[nst]);
                MBARRIER_ARRIVE_PEER(ready[nst], peer);
            }
        }

        // prefetch KV(t+1): rank-split multicast (wait both CTAs ready)
        if (t < 15 && tid == 0) {
            const size_t kt = (size_t)(bh * 16 + (t + 1));
            MBARRIER_EXPECT_TX(fullKV[nst], 4 * 16384);
            if (t >= 1) { MBAR_WAIT(ready[nst], phR[nst]); phR[nst] ^= 1; }
            if (rank == 0) {
                bulkcp_mc(base + AK(nst),         g_khi  + kt * 8192, 16384, fullKV[nst], 3);
                bulkcp_mc(base + AK(nst) + 16384, g_klo  + kt * 8192, 16384, fullKV[nst], 3);
            } else {
                bulkcp_mc(base + AV(nst),         g_vthi + kt * 8192, 16384, fullKV[nst], 3);
                bulkcp_mc(base + AV(nst) + 16384, g_vtlo + kt * 8192, 16384, fullKV[nst], 3);
            }
        }

        // P = ex2(sv*SCL + bias), sign gate, l accumulate
        float lsum = 0.f;
#pragma unroll
        for (int j2 = 0; j2 < 32; j2++) {
            float2 bz = __half22float2(hb[j2]);
            float p0 = ex2_fast(fmaf(sv[2*j2],     SCL, bz.x));
            float p1 = ex2_fast(fmaf(sv[2*j2 + 1], SCL, bz.y));
            lsum += p0 + p1;
            sv[2*j2]     = (bz.x < 0.f) ? -p0 : p0;
            sv[2*j2 + 1] = (bz.y < 0.f) ? -p1 : p1;
        }
        l += lsum;

        // write P (hi/lo, STS.128)
        {
            const int pco = AP + g * 16384;
#pragma unroll
            for (int jg = 0; jg < 8; jg++) {
                uint32_t H[4], L[4];
#pragma unroll
                for (int e = 0; e < 4; e++) {
                    float f0 = sv[jg * 8 + e * 2], f1 = sv[jg * 8 + e * 2 + 1];
                    uint32_t hh;
                    asm("cvt.rn.bf16x2.f32 %0, %1, %2;" : "=r"(hh) : "f"(f1), "f"(f0));
                    __nv_bfloat162 hv = *(__nv_bfloat162*)&hh;
                    float r0 = f0 - __bfloat162float(hv.x);
                    float r1 = f1 - __bfloat162float(hv.y);
                    uint32_t ll;
                    asm("cvt.rn.bf16x2.f32 %0, %1, %2;" : "=r"(ll) : "f"(r1), "f"(r0));
                    H[e] = hh; L[e] = ll;
                }
                const uint32_t off = swz((uint32_t)(row * 128 + jg * 16));
                *(uint4*)(smp + pco + off) = make_uint4(H[0], H[1], H[2], H[3]);
                *(uint4*)(smp + pco + 32768 + off) = make_uint4(L[0], L[1], L[2], L[3]);
            }
        }
        __syncthreads();   // P visible

        // S(t+1) first, then PV(t)
        if (tid == 0) {
            asm volatile("fence.proxy.async.shared::cta;" ::: "memory");
            TCGEN05_FENCE_AFTER();
            if (t < 15) {
                if (nst == 0) { MBAR_WAIT(fullKV[0], phF0); phF0 ^= 1; }
                else          { MBAR_WAIT(fullKV[1], phF1); phF1 ^= 1; }
                const uint64_t dQh = make_desc_sw128(base + AQ_H);
                const uint64_t dQl = make_desc_sw128(base + AQ_L);
                const uint64_t dKh = make_desc_sw128(base + AK(nst));
                const uint64_t dKl = make_desc_sw128(base + AK(nst) + 16384);
                const uint32_t sd = tmem + nst * 128;
#pragma unroll
                for (int ks = 0; ks < 4; ks++) mma_f16_ss(sd, dQh + ks*2, dKh + ks*2, IDESC_S, ks > 0);
#pragma unroll
                for (int ks = 0; ks < 4; ks++) mma_f16_ss(sd, dQh + ks*2, dKl + ks*2, IDESC_S, 1);
#pragma unroll
                for (int ks = 0; ks < 4; ks++) mma_f16_ss(sd, dQl + ks*2, dKh + ks*2, IDESC_S, 1);
                TCGEN05_COMMIT(mbS);
            }
            const uint32_t vst = base + AV(stg);
#pragma unroll
            for (int c = 0; c < 2; c++) {
                const uint64_t dPh = make_desc_sw128(base + AP + c * 16384);
                const uint64_t dPl = make_desc_sw128(base + AP + 32768 + c * 16384);
                const uint64_t dVh = make_desc_sw128(vst + c * 8192);
                const uint64_t dVl = make_desc_sw128(vst + 16384 + c * 8192);
#pragma unroll
                for (int ks = 0; ks < 4; ks++)
                    mma_f16_ss(tmem + 256, dPh + ks*2, dVh + ks*2, IDESC_PV,
                               !(t == 0 && c == 0 && ks == 0));
#pragma unroll
                for (int ks = 0; ks < 4; ks++)
                    mma_f16_ss(tmem + 256, dPh + ks*2, dVl + ks*2, IDESC_PV, 1);
#pragma unroll
                for (int ks = 0; ks < 4; ks++)
                    mma_f16_ss(tmem + 256, dPl + ks*2, dVh + ks*2, IDESC_PV, 1);
            }
            TCGEN05_COMMIT(mbP);
        }
    }

    // final: O readback + l combine + packed write
    MBAR_WAIT(mbP, phP);
    TCGEN05_FENCE_AFTER();
    float O[32];
    {
        uint32_t r32[32];
        TCGEN05_LD_X32(r32, tmem + 256 + g * 32);
        TCGEN05_WAIT_LD();
#pragma unroll
        for (int i = 0; i < 32; i++) O[i] = __uint_as_float(r32[i]);
    }
    TCGEN05_FENCE_BEFORE();
    __syncthreads();
    sm_red[g][row] = l;
    __syncthreads();
    const float inv = 1.f / (l + sm_red[1 - g][row]);
    const int m = (q0 + row) * 2 + b;
#pragma unroll
    for (int i = 0; i < 16; i++) {
        const int kcol = h * 64 + g * 32 + 2 * i;
        float v0 = O[2 * i] * inv, v1 = O[2 * i + 1] * inv;
        __nv_bfloat162 H, L;
        H.x = __float2bfloat16_rn(v0);
        H.y = __float2bfloat16_rn(v1);
        L.x = __float2bfloat16_rn(v0 - __bfloat162float(H.x));
        L.y = __float2bfloat16_rn(v1 - __bfloat162float(H.y));
        const size_t o = act_off(m, kcol);
        *(__nv_bfloat162*)&g_atthi[o] = H;
        *(__nv_bfloat162*)&g_attlo[o] = L;
    }
    __syncthreads();
    if (wid == 0) TCGEN05_DEALLOC(tmem, 512);
    CLUSTER_SYNC();
#else
    // naive fallback (generic pass only; never executed on GB300)
    const int tid = threadIdx.x;
    if (tid >= 128) return;
    const int bh = blockIdx.y, b = bh >> 4, h = bh & 15;
    const int q = blockIdx.x * 128 + tid;
    float l = 0.f, O[64];
    for (int i = 0; i < 64; i++) O[i] = 0.f;
    for (int k = 0; k < S_LEN; k++) {
        float dot = 0.f;
        for (int d = 0; d < 64; d++) {
            float qv = __bfloat162float(g_qhi[qk_off(bh, q, d)]) +
                       __bfloat162float(g_qlo[qk_off(bh, q, d)]);
            float kv = __bfloat162float(g_khi[qk_off(bh, k, d)]) +
                       __bfloat162float(g_klo[qk_off(bh, k, d)]);
            dot = fmaf(qv, kv, dot);
        }
        float bzs = __half2float(g_bias2h[(size_t)q * S_LEN + k]);
        float e = exp2f(fmaf(dot, SCL, bzs));
        l += e;
        float pe = (bzs < 0.f) ? -e : e;
        for (int d = 0; d < 64; d++) {
            float vv = g_v[(size_t)(k * 2 + b) * DMODEL + h * 64 + d];
            O[d] = fmaf(pe, vv, O[d]);
        }
    }
    const int m = q * 2 + b;
    for (int d = 0; d < 64; d++) {
        float v = O[d] / l;
        bf16 hv = __float2bfloat16_rn(v);
        const size_t o = act_off(m, h * 64 + d);
        g_atthi[o] = hv;
        g_attlo[o] = __float2bfloat16_rn(v - __bfloat162float(hv));
    }
#endif
}

// ------------------------------ launch -------------------------------------
extern "C" void kernel_launch(void* const* d_in, const int* in_sizes, int n_in,
                              void* d_out, int out_size)
{
    const float* src    = (const float*)d_in[0];
    const float* bias2d = (const float*)d_in[1];
    const float* wq = (const float*)d_in[2];
    const float* bq = (const float*)d_in[3];
    const float* wk = (const float*)d_in[4];
    const float* bk = (const float*)d_in[5];
    const float* wv = (const float*)d_in[6];
    const float* bv = (const float*)d_in[7];
    const float* wo = (const float*)d_in[8];
    const float* bo = (const float*)d_in[9];
    float* out = (float*)d_out;

    cudaFuncSetAttribute(qkv_kernel,
                         cudaFuncAttributeMaxDynamicSharedMemorySize, GEMM_SMEM);
    cudaFuncSetAttribute(outproj_kernel,
                         cudaFuncAttributeMaxDynamicSharedMemorySize, GEMM_SMEM);
    cudaFuncSetAttribute(attn_tc_kernel,
                         cudaFuncAttributeMaxDynamicSharedMemorySize, ATTN_DYN);

    bf16 *srchi, *srclo;
    cudaGetSymbolAddress((void**)&srchi, g_srchi);
    cudaGetSymbolAddress((void**)&srclo, g_srclo);

    split_kernel<<<(M_ROWS * DMODEL / 8) / 256, 256>>>(src, srchi, srclo);
    bscale_kernel<<<(S_LEN * S_LEN / 4) / 256, 256>>>(bias2d);
    wprep_kernel<<<dim3(32, 32, 4), dim3(32, 8)>>>(wq, wk, wv, wo);

    dim3 gg(DMODEL / GT_N, M_ROWS / GT_M, 3);
    qkv_kernel<<<gg, GTHREADS, GEMM_SMEM>>>(bq, bk, bv);

    vtrans_kernel<<<dim3(S_LEN / 128, NBH), 256>>>();

    attn_tc_kernel<<<dim3(S_LEN / 128, NBH), 256, ATTN_DYN>>>();

    dim3 go(DMODEL / GT_N, M_ROWS / GT_M);
    outproj_kernel<<<go, GTHREADS, GEMM_SMEM>>>(bo, out);
}

// round 14
// speedup vs baseline: 1.0980x; 1.0980x over previous
#include <cuda_runtime.h>
#include <cuda_bf16.h>
#include <math.h>
#include <stdint.h>
#include <stddef.h>

#define S_LEN  2048
#define BATCH  2
#define DMODEL 1024
#define NHEADS 16
#define HDIM   64
#define M_ROWS 4096
#define NBH    (BATCH * NHEADS)
#define SCL    0.18033688011112042f   // 0.125 * log2(e)
#define LOG2E  1.4426950408889634f

typedef __nv_bfloat16 bf16;

#if defined(__CUDA_ARCH__) && (defined(__CUDA_ARCH_SPECIFIC__) || \
    defined(__CUDA_ARCH_FEAT_SM103_ALL) || defined(__CUDA_ARCH_FEAT_SM100_ALL))
#define TC_OK 1
#else
#define TC_OK 0
#endif

// ------------------------------ scratch (tile-packed) ----------------------
__device__ __align__(128) bf16 g_srchi[M_ROWS * DMODEL];
__device__ __align__(128) bf16 g_srclo[M_ROWS * DMODEL];
__device__ __align__(128) bf16 g_atthi[M_ROWS * DMODEL];
__device__ __align__(128) bf16 g_attlo[M_ROWS * DMODEL];
__device__ __align__(128) bf16 g_whi[4][DMODEL * DMODEL];
__device__ __align__(128) bf16 g_wlo[4][DMODEL * DMODEL];
__device__ __align__(128) bf16 g_qhi[NBH * S_LEN * HDIM];
__device__ __align__(128) bf16 g_qlo[NBH * S_LEN * HDIM];
__device__ __align__(128) bf16 g_khi[NBH * S_LEN * HDIM];
__device__ __align__(128) bf16 g_klo[NBH * S_LEN * HDIM];
__device__ __align__(128) bf16 g_vthi[NBH * HDIM * S_LEN];
__device__ __align__(128) bf16 g_vtlo[NBH * HDIM * S_LEN];
__device__ float g_v[M_ROWS * DMODEL];
// bias * log2(e), packed per (qtile, ktile) as [k(128)][q(128)] fp32 64KB tiles
__device__ __align__(128) float g_bias2[S_LEN * S_LEN];

// ------------------------------ helpers ------------------------------------
__device__ __forceinline__ uint32_t smem_u32(const void* p) {
    uint32_t a;
    asm("{ .reg .u64 t; cvta.to.shared.u64 t, %1; cvt.u32.u64 %0, t; }"
        : "=r"(a) : "l"(p));
    return a;
}
__device__ __forceinline__ float ex2_fast(float x) {
    float r;
    asm("ex2.approx.ftz.f32 %0, %1;" : "=f"(r) : "f"(x));
    return r;
}
__device__ __forceinline__ uint32_t swz(uint32_t off) {
    return off ^ ((off >> 3) & 0x70);
}
__device__ __forceinline__ void bulkcp(uint32_t dst, const void* src,
                                       uint32_t bytes, uint32_t mbar) {
    asm volatile(
        "cp.async.bulk.shared::cluster.global.mbarrier::complete_tx::bytes "
        "[%0], [%1], %2, [%3];"
        :: "r"(dst), "l"(src), "r"(bytes), "r"(mbar) : "memory");
}
#define MBARRIER_INIT(mb, c) \
    asm volatile("mbarrier.init.shared.b64 [%0], %1;" :: "r"((uint32_t)(mb)), "r"((uint32_t)(c)) : "memory")
#define MBARRIER_EXPECT_TX(mb, tx) \
    asm volatile("mbarrier.arrive.expect_tx.shared.b64 _, [%0], %1;" \
                 :: "r"((uint32_t)(mb)), "r"((uint32_t)(tx)) : "memory")
#define MBAR_WAIT(mb, par) do {                                                  \
    uint32_t _m = (uint32_t)(mb); uint32_t _p = (uint32_t)(par); uint32_t _d;    \
    asm volatile("{\n\t.reg .pred p;\n\t"                                        \
        "mbarrier.try_wait.parity.acquire.cta.shared::cta.b64 p, [%1], %2;\n\t"  \
        "selp.b32 %0, 1, 0, p;\n\t}" : "=r"(_d) : "r"(_m), "r"(_p) : "memory");  \
    if (!_d) {                                                                   \
        asm volatile("{\n\t.reg .pred P1;\n\tWL_%=:\n\t"                         \
            "mbarrier.try_wait.parity.acquire.cta.shared::cta.b64 P1, [%0], %1, 0x989680;\n\t" \
            "@P1 bra.uni WD_%=;\n\tbra.uni WL_%=;\n\tWD_%=:\n\t}"                \
            :: "r"(_m), "r"(_p) : "memory");                                     \
    } } while (0)

// ---- packed-layout index helpers ----
__device__ __forceinline__ size_t act_off(int m, int k) {
    uint32_t byte = swz((uint32_t)((((m & 127) * 8) + ((k & 63) >> 3)) * 16)) + (k & 7) * 2;
    return ((size_t)((m >> 7) * 16 + (k >> 6))) * 8192 + (byte >> 1);
}
__device__ __forceinline__ size_t w_off(int n, int k) {
    uint32_t byte = (uint32_t)(((n >> 7) & 1) * 16384)
                  + swz((uint32_t)((((n & 127) * 8) + ((k & 63) >> 3)) * 16)) + (k & 7) * 2;
    return ((size_t)((n >> 8) * 16 + (k >> 6))) * 16384 + (byte >> 1);
}
__device__ __forceinline__ size_t qk_off(int bh, int s, int d) {
    uint32_t byte = swz((uint32_t)((((s & 127) * 8) + (d >> 3)) * 16)) + (d & 7) * 2;
    return ((size_t)(bh * 16 + (s >> 7))) * 8192 + (byte >> 1);
}
__device__ __forceinline__ size_t v_off(int bh, int s, int d) {
    uint32_t byte = (uint32_t)(((s & 127) >> 6) * 8192)
                  + swz((uint32_t)((d * 8 + ((s & 63) >> 3)) * 16)) + (s & 7) * 2;
    return ((size_t)(bh * 16 + (s >> 7))) * 8192 + (byte >> 1);
}

#if TC_OK
#define TCGEN05_ALLOC(sa, n) \
    asm volatile("tcgen05.alloc.cta_group::1.sync.aligned.shared::cta.b32 [%0], %1;" \
                 :: "r"((uint32_t)(sa)), "r"((uint32_t)(n)) : "memory")
#define TCGEN05_DEALLOC(t, n) \
    asm volatile("tcgen05.dealloc.cta_group::1.sync.aligned.b32 %0, %1;" :: "r"(t), "r"((uint32_t)(n)))
#define TCGEN05_RELINQ() \
    asm volatile("tcgen05.relinquish_alloc_permit.cta_group::1.sync.aligned;")
#define TCGEN05_COMMIT(mb) \
    asm volatile("tcgen05.commit.cta_group::1.mbarrier::arrive::one.shared::cluster.b64 [%0];" \
                 :: "r"((uint32_t)(mb)) : "memory")
#define TCGEN05_FENCE_AFTER()  asm volatile("tcgen05.fence::after_thread_sync;" ::: "memory")
#define TCGEN05_FENCE_BEFORE() asm volatile("tcgen05.fence::before_thread_sync;" ::: "memory")
#define TCGEN05_WAIT_LD()      asm volatile("tcgen05.wait::ld.sync.aligned;" ::: "memory")
#define TCGEN05_LD_X32(r, ta) \
    asm volatile("tcgen05.ld.sync.aligned.32x32b.x32.b32 " \
        "{%0,%1,%2,%3,%4,%5,%6,%7,%8,%9,%10,%11,%12,%13,%14,%15," \
        "%16,%17,%18,%19,%20,%21,%22,%23,%24,%25,%26,%27,%28,%29,%30,%31}, [%32];" \
        : "=r"((r)[0]),"=r"((r)[1]),"=r"((r)[2]),"=r"((r)[3]),"=r"((r)[4]),"=r"((r)[5]),"=r"((r)[6]),"=r"((r)[7]), \
          "=r"((r)[8]),"=r"((r)[9]),"=r"((r)[10]),"=r"((r)[11]),"=r"((r)[12]),"=r"((r)[13]),"=r"((r)[14]),"=r"((r)[15]), \
          "=r"((r)[16]),"=r"((r)[17]),"=r"((r)[18]),"=r"((r)[19]),"=r"((r)[20]),"=r"((r)[21]),"=r"((r)[22]),"=r"((r)[23]), \
          "=r"((r)[24]),"=r"((r)[25]),"=r"((r)[26]),"=r"((r)[27]),"=r"((r)[28]),"=r"((r)[29]),"=r"((r)[30]),"=r"((r)[31]) \
        : "r"(ta))

static __device__ __forceinline__ uint64_t make_desc_sw128(uint32_t base) {
    const uint64_t B = (uint64_t(2) << 61) | (uint64_t(1) << 46)
                     | (uint64_t(64) << 32) | (uint64_t(1) << 16);
    return B | ((uint64_t)(base >> 4) & 0x3FFF);
}
__device__ __forceinline__ void mma_f16_ss(uint32_t d, uint64_t a, uint64_t b,
                                           uint32_t idesc, uint32_t en) {
    asm volatile("{\n\t.reg .pred p;\n\tsetp.ne.u32 p, %5, 0;\n\t"
        "tcgen05.mma.cta_group::1.kind::f16 [%0], %1, %2, %3, {%4,%4,%4,%4}, p;\n\t}"
        :: "r"(d), "l"(a), "l"(b), "r"(idesc), "r"(0u), "r"(en) : "memory");
}
#endif // TC_OK

// ------------------------------ prep kernels -------------------------------
__global__ void split_kernel(const float* __restrict__ in,
                             bf16* __restrict__ hi, bf16* __restrict__ lo)
{
    int idx = blockIdx.x * blockDim.x + threadIdx.x;
    int m = idx >> 7, k = (idx & 127) * 8;
    float4 a = *(const float4*)&in[(size_t)m * DMODEL + k];
    float4 b = *(const float4*)&in[(size_t)m * DMODEL + k + 4];
    float f[8] = {a.x, a.y, a.z, a.w, b.x, b.y, b.z, b.w};
    uint32_t H[4], L[4];
#pragma unroll
    for (int e = 0; e < 4; e++) {
        uint32_t hh;
        asm("cvt.rn.bf16x2.f32 %0, %1, %2;" : "=r"(hh) : "f"(f[2*e+1]), "f"(f[2*e]));
        __nv_bfloat162 hv = *(__nv_bfloat162*)&hh;
        float r0 = f[2*e]   - __bfloat162float(hv.x);
        float r1 = f[2*e+1] - __bfloat162float(hv.y);
        uint32_t ll;
        asm("cvt.rn.bf16x2.f32 %0, %1, %2;" : "=r"(ll) : "f"(r1), "f"(r0));
        H[e] = hh; L[e] = ll;
    }
    size_t off = act_off(m, k);
    *(uint4*)&hi[off] = make_uint4(H[0], H[1], H[2], H[3]);
    *(uint4*)&lo[off] = make_uint4(L[0], L[1], L[2], L[3]);
}

// bias transpose-pack: in[q][k] -> g_bias2 tiles [qt][kt][k(128)][q(128)], *log2e
__global__ void btrans_kernel(const float* __restrict__ in)
{
    __shared__ float t[32][33];
    const int kb = blockIdx.x, qb = blockIdx.y;   // 32x32 blocks
    const int tx = threadIdx.x, ty = threadIdx.y; // 32x8
#pragma unroll
    for (int i = 0; i < 4; i++)
        t[ty + i * 8][tx] = in[(size_t)(qb * 32 + ty + i * 8) * S_LEN + kb * 32 + tx] * LOG2E;
    __syncthreads();
    const size_t tb = ((size_t)((qb >> 2) * 16 + (kb >> 2))) * 16384;
#pragma unroll
    for (int i = 0; i < 4; i++) {
        const int k = kb * 32 + ty + i * 8;
        g_bias2[tb + (size_t)(k & 127) * 128 + (qb & 3) * 32 + tx] = t[tx][ty + i * 8];
    }
}

__global__ void wprep_kernel(const float* __restrict__ w0, const float* __restrict__ w1,
                             const float* __restrict__ w2, const float* __restrict__ w3)
{
    __shared__ float t[32][33];
    const float* W = (blockIdx.z == 0) ? w0 : (blockIdx.z == 1) ? w1
                   : (blockIdx.z == 2) ? w2 : w3;
    bf16* Whi = g_whi[blockIdx.z];
    bf16* Wlo = g_wlo[blockIdx.z];
    const int n0 = blockIdx.x * 32, k0 = blockIdx.y * 32;
    const int tx = threadIdx.x, ty = threadIdx.y;
#pragma unroll
    for (int i = 0; i < 4; i++)
        t[ty + i * 8][tx] = W[(size_t)(k0 + ty + i * 8) * DMODEL + n0 + tx];
    __syncthreads();
#pragma unroll
    for (int i = 0; i < 4; i++) {
        const int n = n0 + ty + i * 8, k = k0 + tx;
        float v = t[tx][ty + i * 8];
        bf16 h = __float2bfloat16_rn(v);
        size_t o = w_off(n, k);
        Whi[o] = h;
        Wlo[o] = __float2bfloat16_rn(v - __bfloat162float(h));
    }
}

__global__ __launch_bounds__(256)
void vtrans_kernel()
{
    __shared__ float t[64][65];
    const int bh = blockIdx.y, b = bh >> 4, h = bh & 15;
    const int s0 = blockIdx.x * 128;
    const int tid = threadIdx.x;
    for (int half = 0; half < 2; half++) {
        __syncthreads();
#pragma unroll
        for (int p = 0; p < 16; p++) {
            const int idx = tid + p * 256;
            const int d = idx & 63, sl = idx >> 6;
            t[d][sl] = g_v[(size_t)((s0 + half * 64 + sl) * 2 + b) * DMODEL + h * 64 + d];
        }
        __syncthreads();
#pragma unroll
        for (int p = 0; p < 8; p++) {
            const int idx = tid + p * 256;
            const int sp2 = idx & 31, d = idx >> 5;
            const int s = s0 + half * 64 + sp2 * 2;
            float v0 = t[d][sp2 * 2], v1 = t[d][sp2 * 2 + 1];
            __nv_bfloat162 H, L;
            H.x = __float2bfloat16_rn(v0);
            H.y = __float2bfloat16_rn(v1);
            L.x = __float2bfloat16_rn(v0 - __bfloat162float(H.x));
            L.y = __float2bfloat16_rn(v1 - __bfloat162float(H.y));
            const size_t o = v_off(bh, s, d);
            *(__nv_bfloat162*)&g_vthi[o] = H;
            *(__nv_bfloat162*)&g_vtlo[o] = L;
        }
    }
}

// --------------- tcgen05 GEMM (128x256, 2-stage, bulk-copy) ----------------
#define GTHREADS 512
#define GT_M 128
#define GT_N 256
#define GT_K 64
#define NCHUNK (DMODEL / GT_K)
#define OFF_AH 0
#define OFF_AL 16384
#define OFF_BH 32768
#define OFF_BL 65536
#define STAGE_B 98304
#define GEMM_SMEM (2 * STAGE_B + 1024)
#define GT_IDESC ((1u<<4)|(1u<<7)|(1u<<10)|(16u<<17)|(8u<<24))

__device__ __forceinline__ void gemm_core(
    const bf16* __restrict__ Ah, const bf16* __restrict__ Al,
    const bf16* __restrict__ Bh, const bf16* __restrict__ Bl,
    const float* __restrict__ bias, float* __restrict__ outf,
    bf16* __restrict__ outhi, bf16* __restrict__ outlo, int mode,
    char* dyn, uint32_t* s_tmem_p, uint64_t* s_mbar)
{
#if TC_OK
    const int tid = threadIdx.x, wid = tid >> 5, lid = tid & 31;
    const int n0 = blockIdx.x * GT_N, m0 = blockIdx.y * GT_M;
    const int mt = m0 >> 7, nt = n0 >> 8;

    uint32_t base = smem_u32(dyn);
    base = (base + 1023u) & ~1023u;
    const uint32_t full[2] = { smem_u32(&s_mbar[0]), smem_u32(&s_mbar[1]) };
    const uint32_t mmb[2]  = { smem_u32(&s_mbar[2]), smem_u32(&s_mbar[3]) };

    if (wid == 0) { TCGEN05_ALLOC(smem_u32(s_tmem_p), 256); TCGEN05_RELINQ(); }
    if (tid == 0) {
        MBARRIER_INIT(full[0], 1); MBARRIER_INIT(full[1], 1);
        MBARRIER_INIT(mmb[0], 1);  MBARRIER_INIT(mmb[1], 1);
    }
    __syncthreads();
    const uint32_t tmem = *s_tmem_p;

    if (tid == 0) {
#pragma unroll
        for (int c0 = 0; c0 < 2; c0++) {
            const uint32_t ss = base + c0 * STAGE_B;
            MBARRIER_EXPECT_TX(full[c0], (uint32_t)STAGE_B);
            bulkcp(ss + OFF_AH, Ah + (size_t)(mt * 16 + c0) * 8192,  16384, full[c0]);
            bulkcp(ss + OFF_AL, Al + (size_t)(mt * 16 + c0) * 8192,  16384, full[c0]);
            bulkcp(ss + OFF_BH, Bh + (size_t)(nt * 16 + c0) * 16384, 32768, full[c0]);
            bulkcp(ss + OFF_BL, Bl + (size_t)(nt * 16 + c0) * 16384, 32768, full[c0]);
        }
        int phF[2] = {0, 0}, phM[2] = {0, 0};
        for (int c = 0; c < NCHUNK; c++) {
            const int s = c & 1;
            const uint32_t ss = base + s * STAGE_B;
            MBAR_WAIT(full[s], phF[s]); phF[s] ^= 1;
            const uint64_t dAh = make_desc_sw128(ss + OFF_AH);
            const uint64_t dAl = make_desc_sw128(ss + OFF_AL);
#pragma unroll
            for (int sub = 0; sub < 2; sub++) {
                const uint64_t dBh = make_desc_sw128(ss + OFF_BH + sub * 16384);
                const uint64_t dBl = make_desc_sw128(ss + OFF_BL + sub * 16384);
                const uint32_t dst = tmem + sub * 128;
#pragma unroll
                for (int ks = 0; ks < 4; ks++)
                    mma_f16_ss(dst, dAh + ks * 2, dBh + ks * 2, GT_IDESC,
                               (c == 0 && ks == 0) ? 0u : 1u);
#pragma unroll
                for (int ks = 0; ks < 4; ks++)
                    mma_f16_ss(dst, dAh + ks * 2, dBl + ks * 2, GT_IDESC, 1u);
#pragma unroll
                for (int ks = 0; ks < 4; ks++)
                    mma_f16_ss(dst, dAl + ks * 2, dBh + ks * 2, GT_IDESC, 1u);
            }
            TCGEN05_COMMIT(mmb[s]);
            if (c + 2 < NCHUNK) {
                MBAR_WAIT(mmb[s], phM[s]); phM[s] ^= 1;
                MBARRIER_EXPECT_TX(full[s], (uint32_t)STAGE_B);
                bulkcp(ss + OFF_AH, Ah + (size_t)(mt * 16 + c + 2) * 8192,  16384, full[s]);
                bulkcp(ss + OFF_AL, Al + (size_t)(mt * 16 + c + 2) * 8192,  16384, full[s]);
                bulkcp(ss + OFF_BH, Bh + (size_t)(nt * 16 + c + 2) * 16384, 32768, full[s]);
                bulkcp(ss + OFF_BL, Bl + (size_t)(nt * 16 + c + 2) * 16384, 32768, full[s]);
            }
        }
        MBAR_WAIT(mmb[0], phM[0]);
        MBAR_WAIT(mmb[1], phM[1]);
    }
    __syncthreads();
    TCGEN05_FENCE_AFTER();

    {
        const int m = m0 + (wid & 3) * 32 + lid;
        const int s = m >> 1, b = m & 1;
#pragma unroll
        for (int gg = 0; gg < 2; gg++) {
            const int g = (wid >> 2) + gg * 4;
            uint32_t r[32];
            TCGEN05_LD_X32(r, tmem + g * 32);
            TCGEN05_WAIT_LD();
            const int cb = n0 + g * 32;
            if (mode == 0) {
#pragma unroll
                for (int q = 0; q < 8; q++) {
                    float4 v;
                    v.x = __uint_as_float(r[q * 4 + 0]) + bias[cb + q * 4 + 0];
                    v.y = __uint_as_float(r[q * 4 + 1]) + bias[cb + q * 4 + 1];
                    v.z = __uint_as_float(r[q * 4 + 2]) + bias[cb + q * 4 + 2];
                    v.w = __uint_as_float(r[q * 4 + 3]) + bias[cb + q * 4 + 3];
                    *(float4*)&outf[(size_t)m * DMODEL + cb + q * 4] = v;
                }
            } else {
                const int h = cb >> 6;
                const int bh = b * NHEADS + h;
#pragma unroll
                for (int q = 0; q < 16; q++) {
                    const int co = cb + q * 2;
                    float v0 = __uint_as_float(r[q * 2 + 0]) + bias[co + 0];
                    float v1 = __uint_as_float(r[q * 2 + 1]) + bias[co + 1];
                    __nv_bfloat162 H, L;
                    H.x = __float2bfloat16_rn(v0);
                    H.y = __float2bfloat16_rn(v1);
                    L.x = __float2bfloat16_rn(v0 - __bfloat162float(H.x));
                    L.y = __float2bfloat16_rn(v1 - __bfloat162float(H.y));
                    const size_t o = qk_off(bh, s, co & 63);
                    *(__nv_bfloat162*)&outhi[o] = H;
                    *(__nv_bfloat162*)&outlo[o] = L;
                }
            }
        }
        TCGEN05_FENCE_BEFORE();
    }
    __syncthreads();
    if (wid == 0) TCGEN05_DEALLOC(tmem, 256);
#else
    const int tid = threadIdx.x;
    const int n0 = blockIdx.x * GT_N, m0 = blockIdx.y * GT_M;
    for (int idx = tid; idx < GT_M * GT_N; idx += GTHREADS) {
        const int m = m0 + idx / GT_N, n = n0 + idx % GT_N;
        float sacc = bias[n];
        for (int k = 0; k < DMODEL; k++) {
            float a = __bfloat162float(Ah[act_off(m, k)]) +
                      __bfloat162float(Al[act_off(m, k)]);
            float bb = __bfloat162float(Bh[w_off(n, k)]) +
                       __bfloat162float(Bl[w_off(n, k)]);
            sacc = fmaf(a, bb, sacc);
        }
        if (mode == 0) outf[(size_t)m * DMODEL + n] = sacc;
        else {
            const int s = m >> 1, b = m & 1, h = n >> 6, d = n & 63;
            const size_t o = qk_off(b * NHEADS + h, s, d);
            bf16 hv = __float2bfloat16_rn(sacc);
            outhi[o] = hv;
            outlo[o] = __float2bfloat16_rn(sacc - __bfloat162float(hv));
        }
    }
#endif
}

__global__ __launch_bounds__(GTHREADS, 1)
void qkv_kernel(const float* __restrict__ bq, const float* __restrict__ bk,
                const float* __restrict__ bv)
{
    extern __shared__ char dyn[];
    __shared__ uint32_t s_tmem;
    __shared__ uint64_t s_mbar[4];
    const int z = blockIdx.z;
    if (z == 0)
        gemm_core(g_srchi, g_srclo, g_whi[0], g_wlo[0], bq, nullptr,
                  g_qhi, g_qlo, 1, dyn, &s_tmem, s_mbar);
    else if (z == 1)
        gemm_core(g_srchi, g_srclo, g_whi[1], g_wlo[1], bk, nullptr,
                  g_khi, g_klo, 1, dyn, &s_tmem, s_mbar);
    else
        gemm_core(g_srchi, g_srclo, g_whi[2], g_wlo[2], bv, g_v,
                  nullptr, nullptr, 0, dyn, &s_tmem, s_mbar);
}

__global__ __launch_bounds__(GTHREADS, 1)
void outproj_kernel(const float* __restrict__ bo, float* __restrict__ out)
{
    extern __shared__ char dyn[];
    __shared__ uint32_t s_tmem;
    __shared__ uint64_t s_mbar[4];
    gemm_core(g_atthi, g_attlo, g_whi[3], g_wlo[3], bo, out,
              nullptr, nullptr, 0, dyn, &s_tmem, s_mbar);
}

// --------------------------- tcgen05 attention -----------------------------
// TMEM: S0 @0-127, S1 @128-255, O @256-319.
#define AQ_H  0
#define AQ_L  16384
#define AK(s) (32768 + (s) * 32768)
#define AV(s) (98304 + (s) * 32768)
#define AP    163840
#define ATTN_DYN (229376 + 1024)
#define IDESC_S  ((1u<<4)|(1u<<7)|(1u<<10)|(16u<<17)|(8u<<24))
#define IDESC_PV ((1u<<4)|(1u<<7)|(1u<<10)|(8u<<17)|(8u<<24))

__global__ __launch_bounds__(256, 1)
void attn_tc_kernel()
{
#if TC_OK
    extern __shared__ char dyn[];
    __shared__ uint32_t s_tmem;
    __shared__ uint64_t s_mb[4];   // mbS, mbP, fullKV0, fullKV1
    __shared__ float sm_red[2][128];

    const int tid = threadIdx.x, wid = tid >> 5, lid = tid & 31;
    const int g = wid >> 2;
    const int sp = wid & 3;
    const int row = sp * 32 + lid;
    const int bh = blockIdx.y;
    const int b = bh >> 4, h = bh & 15;
    const int q0 = blockIdx.x * 128;

    uint32_t base = smem_u32(dyn);
    base = (base + 1023u) & ~1023u;
    char* smp = dyn + (ptrdiff_t)(base - smem_u32(dyn));
    const uint32_t mbS = smem_u32(&s_mb[0]), mbP = smem_u32(&s_mb[1]);
    const uint32_t fullKV[2] = { smem_u32(&s_mb[2]), smem_u32(&s_mb[3]) };

    if (wid == 0) { TCGEN05_ALLOC(smem_u32(&s_tmem), 512); TCGEN05_RELINQ(); }
    if (tid == 0) {
        MBARRIER_INIT(mbS, 1); MBARRIER_INIT(mbP, 1);
        MBARRIER_INIT(fullKV[0], 1); MBARRIER_INIT(fullKV[1], 1);
    }
    __syncthreads();
    const uint32_t tmem = s_tmem;

    int phF0 = 0, phF1 = 0;
    // ---- prologue: Q + K0 + V0 via bulk, then S(0) ----
    if (tid == 0) {
        MBARRIER_EXPECT_TX(fullKV[0], 6 * 16384);
        bulkcp(base + AQ_H, g_qhi + (size_t)(bh * 16 + (q0 >> 7)) * 8192, 16384, fullKV[0]);
        bulkcp(base + AQ_L, g_qlo + (size_t)(bh * 16 + (q0 >> 7)) * 8192, 16384, fullKV[0]);
        bulkcp(base + AK(0),          g_khi  + (size_t)(bh * 16) * 8192, 16384, fullKV[0]);
        bulkcp(base + AK(0) + 16384,  g_klo  + (size_t)(bh * 16) * 8192, 16384, fullKV[0]);
        bulkcp(base + AV(0),          g_vthi + (size_t)(bh * 16) * 8192, 16384, fullKV[0]);
        bulkcp(base + AV(0) + 16384,  g_vtlo + (size_t)(bh * 16) * 8192, 16384, fullKV[0]);
        MBAR_WAIT(fullKV[0], 0); phF0 = 1;
        const uint64_t dQh = make_desc_sw128(base + AQ_H);
        const uint64_t dQl = make_desc_sw128(base + AQ_L);
        const uint64_t dKh = make_desc_sw128(base + AK(0));
        const uint64_t dKl = make_desc_sw128(base + AK(0) + 16384);
#pragma unroll
        for (int ks = 0; ks < 4; ks++) mma_f16_ss(tmem, dQh + ks*2, dKh + ks*2, IDESC_S, ks > 0);
#pragma unroll
        for (int ks = 0; ks < 4; ks++) mma_f16_ss(tmem, dQh + ks*2, dKl + ks*2, IDESC_S, 1);
#pragma unroll
        for (int ks = 0; ks < 4; ks++) mma_f16_ss(tmem, dQl + ks*2, dKh + ks*2, IDESC_S, 1);
        TCGEN05_COMMIT(mbS);
    }

    float l = 0.f;
    uint32_t phS = 0, phP = 0;
    const float* bsm = (const float*)(smp + AP);   // staged bias [k][q]

    for (int t = 0; t < 16; t++) {
        const int stg = t & 1;
        const int nst = (t + 1) & 1;

        // --- PV(t-1) done: P region + V stage free ---
        if (t > 0) { MBAR_WAIT(mbP, phP); phP ^= 1; TCGEN05_FENCE_AFTER(); }

        // --- stage bias tile (t) into P region: coalesced 16x float4 ---
        {
            const float4* bsrc = (const float4*)
                (g_bias2 + ((size_t)((q0 >> 7) * 16 + t)) * 16384);
#pragma unroll
            for (int p = 0; p < 16; p++)
                *(float4*)(smp + AP + (size_t)(p * 256 + tid) * 16) = bsrc[p * 256 + tid];
        }

        // --- prefetch KV(t+1): bulk by tid0 ---
        if (t < 15 && tid == 0) {
            const size_t kt = (size_t)(bh * 16 + (t + 1));
            MBARRIER_EXPECT_TX(fullKV[nst], 4 * 16384);
            bulkcp(base + AK(nst),         g_khi  + kt * 8192, 16384, fullKV[nst]);
            bulkcp(base + AK(nst) + 16384, g_klo  + kt * 8192, 16384, fullKV[nst]);
            bulkcp(base + AV(nst),         g_vthi + kt * 8192, 16384, fullKV[nst]);
            bulkcp(base + AV(nst) + 16384, g_vtlo + kt * 8192, 16384, fullKV[nst]);
        }

        // --- S(t) ready; read it ---
        MBAR_WAIT(mbS, phS); phS ^= 1;
        TCGEN05_FENCE_AFTER();
        float sv[64];
        {
            uint32_t r32a[32], r32b[32];
            TCGEN05_LD_X32(r32a, tmem + stg * 128 + g * 64);
            TCGEN05_LD_X32(r32b, tmem + stg * 128 + g * 64 + 32);
            TCGEN05_WAIT_LD();
#pragma unroll
            for (int i = 0; i < 32; i++) sv[i] = __uint_as_float(r32a[i]);
#pragma unroll
            for (int i = 0; i < 32; i++) sv[32 + i] = __uint_as_float(r32b[i]);
            TCGEN05_FENCE_BEFORE();
        }
        __syncthreads();   // bias staged (and S read before anything clobbers)

        // --- P = ex2(sv*SCL + bias), sign gate, l accumulate ---
        float lsum = 0.f;
#pragma unroll
        for (int j = 0; j < 64; j++) {
            float bz = bsm[(size_t)(g * 64 + j) * 128 + row];   // conflict-free
            float pe = ex2_fast(fmaf(sv[j], SCL, bz));
            lsum += pe;
            sv[j] = (bz < 0.f) ? -pe : pe;
        }
        l += lsum;
        __syncthreads();   // all bias reads done before P overwrite

        // --- write P (hi/lo, STS.128) ---
        {
            const int pco = AP + g * 16384;
#pragma unroll
            for (int jg = 0; jg < 8; jg++) {
                uint32_t H[4], L[4];
#pragma unroll
                for (int e = 0; e < 4; e++) {
                    float f0 = sv[jg * 8 + e * 2], f1 = sv[jg * 8 + e * 2 + 1];
                    uint32_t hh;
                    asm("cvt.rn.bf16x2.f32 %0, %1, %2;" : "=r"(hh) : "f"(f1), "f"(f0));
                    __nv_bfloat162 hv = *(__nv_bfloat162*)&hh;
                    float r0 = f0 - __bfloat162float(hv.x);
                    float r1 = f1 - __bfloat162float(hv.y);
                    uint32_t ll;
                    asm("cvt.rn.bf16x2.f32 %0, %1, %2;" : "=r"(ll) : "f"(r1), "f"(r0));
                    H[e] = hh; L[e] = ll;
                }
                const uint32_t off = swz((uint32_t)(row * 128 + jg * 16));
                *(uint4*)(smp + pco + off) = make_uint4(H[0], H[1], H[2], H[3]);
                *(uint4*)(smp + pco + 32768 + off) = make_uint4(L[0], L[1], L[2], L[3]);
            }
        }
        __syncthreads();   // P visible

        // --- S(t+1) first (after KV(t+1) arrives), then PV(t) ---
        if (tid == 0) {
            asm volatile("fence.proxy.async.shared::cta;" ::: "memory");
            TCGEN05_FENCE_AFTER();
            if (t < 15) {
                if (nst == 0) { MBAR_WAIT(fullKV[0], phF0); phF0 ^= 1; }
                else          { MBAR_WAIT(fullKV[1], phF1); phF1 ^= 1; }
                const uint64_t dQh = make_desc_sw128(base + AQ_H);
                const uint64_t dQl = make_desc_sw128(base + AQ_L);
                const uint64_t dKh = make_desc_sw128(base + AK(nst));
                const uint64_t dKl = make_desc_sw128(base + AK(nst) + 16384);
                const uint32_t sd = tmem + nst * 128;
#pragma unroll
                for (int ks = 0; ks < 4; ks++) mma_f16_ss(sd, dQh + ks*2, dKh + ks*2, IDESC_S, ks > 0);
#pragma unroll
                for (int ks = 0; ks < 4; ks++) mma_f16_ss(sd, dQh + ks*2, dKl + ks*2, IDESC_S, 1);
#pragma unroll
                for (int ks = 0; ks < 4; ks++) mma_f16_ss(sd, dQl + ks*2, dKh + ks*2, IDESC_S, 1);
                TCGEN05_COMMIT(mbS);
            }
            const uint32_t vst = base + AV(stg);
#pragma unroll
            for (int c = 0; c < 2; c++) {
                const uint64_t dPh = make_desc_sw128(base + AP + c * 16384);
                const uint64_t dPl = make_desc_sw128(base + AP + 32768 + c * 16384);
                const uint64_t dVh = make_desc_sw128(vst + c * 8192);
                const uint64_t dVl = make_desc_sw128(vst + 16384 + c * 8192);
#pragma unroll
                for (int ks = 0; ks < 4; ks++)
                    mma_f16_ss(tmem + 256, dPh + ks*2, dVh + ks*2, IDESC_PV,
                               !(t == 0 && c == 0 && ks == 0));
#pragma unroll
                for (int ks = 0; ks < 4; ks++)
                    mma_f16_ss(tmem + 256, dPh + ks*2, dVl + ks*2, IDESC_PV, 1);
#pragma unroll
                for (int ks = 0; ks < 4; ks++)
                    mma_f16_ss(tmem + 256, dPl + ks*2, dVh + ks*2, IDESC_PV, 1);
            }
            TCGEN05_COMMIT(mbP);
        }
    }

    // --- final: O readback + l combine + packed write ---
    MBAR_WAIT(mbP, phP);
    TCGEN05_FENCE_AFTER();
    float O[32];
    {
        uint32_t r32[32];
        TCGEN05_LD_X32(r32, tmem + 256 + g * 32);
        TCGEN05_WAIT_LD();
#pragma unroll
        for (int i = 0; i < 32; i++) O[i] = __uint_as_float(r32[i]);
    }
    TCGEN05_FENCE_BEFORE();
    __syncthreads();
    sm_red[g][row] = l;
    __syncthreads();
    const float inv = 1.f / (l + sm_red[1 - g][row]);
    const int m = (q0 + row) * 2 + b;
#pragma unroll
    for (int i = 0; i < 16; i++) {
        const int kcol = h * 64 + g * 32 + 2 * i;
        float v0 = O[2 * i] * inv, v1 = O[2 * i + 1] * inv;
        __nv_bfloat162 H, L;
        H.x = __float2bfloat16_rn(v0);
        H.y = __float2bfloat16_rn(v1);
        L.x = __float2bfloat16_rn(v0 - __bfloat162float(H.x));
        L.y = __float2bfloat16_rn(v1 - __bfloat162float(H.y));
        const size_t o = act_off(m, kcol);
        *(__nv_bfloat162*)&g_atthi[o] = H;
        *(__nv_bfloat162*)&g_attlo[o] = L;
    }
    __syncthreads();
    if (wid == 0) TCGEN05_DEALLOC(tmem, 512);
#else
    // naive fallback (generic pass only; never executed on GB300)
    const int tid = threadIdx.x;
    if (tid >= 128) return;
    const int bh = blockIdx.y, b = bh >> 4, h = bh & 15;
    const int q = blockIdx.x * 128 + tid;
    float l = 0.f, O[64];
    for (int i = 0; i < 64; i++) O[i] = 0.f;
    for (int k = 0; k < S_LEN; k++) {
        float dot = 0.f;
        for (int d = 0; d < 64; d++) {
            float qv = __bfloat162float(g_qhi[qk_off(bh, q, d)]) +
                       __bfloat162float(g_qlo[qk_off(bh, q, d)]);
            float kv = __bfloat162float(g_khi[qk_off(bh, k, d)]) +
                       __bfloat162float(g_klo[qk_off(bh, k, d)]);
            dot = fmaf(qv, kv, dot);
        }
        float bzs = g_bias2[((size_t)((q >> 7) * 16 + (k >> 7))) * 16384
                            + (size_t)(k & 127) * 128 + (q & 127)];
        float e = exp2f(fmaf(dot, SCL, bzs));
        l += e;
        float pe = (bzs < 0.f) ? -e : e;
        for (int d = 0; d < 64; d++) {
            float vv = g_v[(size_t)(k * 2 + b) * DMODEL + h * 64 + d];
            O[d] = fmaf(pe, vv, O[d]);
        }
    }
    const int m = q * 2 + b;
    for (int d = 0; d < 64; d++) {
        float v = O[d] / l;
        bf16 hv = __float2bfloat16_rn(v);
        const size_t o = act_off(m, h * 64 + d);
        g_atthi[o] = hv;
        g_attlo[o] = __float2bfloat16_rn(v - __bfloat162float(hv));
    }
#endif
}

// ------------------------------ launch -------------------------------------
extern "C" void kernel_launch(void* const* d_in, const int* in_sizes, int n_in,
                              void* d_out, int out_size)
{
    const float* src    = (const float*)d_in[0];
    const float* bias2d = (const float*)d_in[1];
    const float* wq = (const float*)d_in[2];
    const float* bq = (const float*)d_in[3];
    const float* wk = (const float*)d_in[4];
    const float* bk = (const float*)d_in[5];
    const float* wv = (const float*)d_in[6];
    const float* bv = (const float*)d_in[7];
    const float* wo = (const float*)d_in[8];
    const float* bo = (const float*)d_in[9];
    float* out = (float*)d_out;

    cudaFuncSetAttribute(qkv_kernel,
                         cudaFuncAttributeMaxDynamicSharedMemorySize, GEMM_SMEM);
    cudaFuncSetAttribute(outproj_kernel,
                         cudaFuncAttributeMaxDynamicSharedMemorySize, GEMM_SMEM);
    cudaFuncSetAttribute(attn_tc_kernel,
                         cudaFuncAttributeMaxDynamicSharedMemorySize, ATTN_DYN);

    bf16 *srchi, *srclo;
    cudaGetSymbolAddress((void**)&srchi, g_srchi);
    cudaGetSymbolAddress((void**)&srclo, g_srclo);

    split_kernel<<<(M_ROWS * DMODEL / 8) / 256, 256>>>(src, srchi, srclo);
    btrans_kernel<<<dim3(S_LEN / 32, S_LEN / 32), dim3(32, 8)>>>(bias2d);
    wprep_kernel<<<dim3(32, 32, 4), dim3(32, 8)>>>(wq, wk, wv, wo);

    dim3 gg(DMODEL / GT_N, M_ROWS / GT_M, 3);
    qkv_kernel<<<gg, GTHREADS, GEMM_SMEM>>>(bq, bk, bv);

    vtrans_kernel<<<dim3(S_LEN / 128, NBH), 256>>>();

    attn_tc_kernel<<<dim3(S_LEN / 128, NBH), 256, ATTN_DYN>>>();

    dim3 go(DMODEL / GT_N, M_ROWS / GT_M);
    outproj_kernel<<<go, GTHREADS, GEMM_SMEM>>>(bo, out);
}

// round 17
// speedup vs baseline: 1.2472x; 1.1359x over previous
#include <cuda_runtime.h>
#include <cuda_bf16.h>
#include <math.h>
#include <stdint.h>
#include <stddef.h>

#define S_LEN  2048
#define BATCH  2
#define DMODEL 1024
#define NHEADS 16
#define HDIM   64
#define M_ROWS 4096
#define NBH    (BATCH * NHEADS)
#define SCL    0.18033688011112042f   // 0.125 * log2(e)
#define LOG2E  1.4426950408889634f

typedef __nv_bfloat16 bf16;

#if defined(__CUDA_ARCH__) && (defined(__CUDA_ARCH_SPECIFIC__) || \
    defined(__CUDA_ARCH_FEAT_SM103_ALL) || defined(__CUDA_ARCH_FEAT_SM100_ALL))
#define TC_OK 1
#else
#define TC_OK 0
#endif

// ------------------------------ scratch (tile-packed) ----------------------
__device__ __align__(128) bf16 g_srchi[M_ROWS * DMODEL];
__device__ __align__(128) bf16 g_srclo[M_ROWS * DMODEL];
__device__ __align__(128) bf16 g_atthi[M_ROWS * DMODEL];
__device__ __align__(128) bf16 g_attlo[M_ROWS * DMODEL];
__device__ __align__(128) bf16 g_whi[4][DMODEL * DMODEL];
__device__ __align__(128) bf16 g_wlo[4][DMODEL * DMODEL];
__device__ __align__(128) bf16 g_qhi[NBH * S_LEN * HDIM];
__device__ __align__(128) bf16 g_qlo[NBH * S_LEN * HDIM];
__device__ __align__(128) bf16 g_khi[NBH * S_LEN * HDIM];
__device__ __align__(128) bf16 g_klo[NBH * S_LEN * HDIM];
__device__ __align__(128) bf16 g_vthi[NBH * HDIM * S_LEN];
__device__ __align__(128) bf16 g_vtlo[NBH * HDIM * S_LEN];
__device__ float g_v[M_ROWS * DMODEL];
// bias * log2(e), packed per (qtile, ktile) as [k(128)][q(128)] fp32 64KB tiles
__device__ __align__(128) float g_bias2[S_LEN * S_LEN];

// ------------------------------ helpers ------------------------------------
__device__ __forceinline__ uint32_t smem_u32(const void* p) {
    uint32_t a;
    asm("{ .reg .u64 t; cvta.to.shared.u64 t, %1; cvt.u32.u64 %0, t; }"
        : "=r"(a) : "l"(p));
    return a;
}
__device__ __forceinline__ float ex2_fast(float x) {
    float r;
    asm("ex2.approx.ftz.f32 %0, %1;" : "=f"(r) : "f"(x));
    return r;
}
__device__ __forceinline__ uint32_t swz(uint32_t off) {
    return off ^ ((off >> 3) & 0x70);
}
__device__ __forceinline__ void bulkcp(uint32_t dst, const void* src,
                                       uint32_t bytes, uint32_t mbar) {
    asm volatile(
        "cp.async.bulk.shared::cluster.global.mbarrier::complete_tx::bytes "
        "[%0], [%1], %2, [%3];"
        :: "r"(dst), "l"(src), "r"(bytes), "r"(mbar) : "memory");
}
#define MBARRIER_INIT(mb, c) \
    asm volatile("mbarrier.init.shared.b64 [%0], %1;" :: "r"((uint32_t)(mb)), "r"((uint32_t)(c)) : "memory")
#define MBARRIER_EXPECT_TX(mb, tx) \
    asm volatile("mbarrier.arrive.expect_tx.shared.b64 _, [%0], %1;" \
                 :: "r"((uint32_t)(mb)), "r"((uint32_t)(tx)) : "memory")
#define MBAR_WAIT(mb, par) do {                                                  \
    uint32_t _m = (uint32_t)(mb); uint32_t _p = (uint32_t)(par); uint32_t _d;    \
    asm volatile("{\n\t.reg .pred p;\n\t"                                        \
        "mbarrier.try_wait.parity.acquire.cta.shared::cta.b64 p, [%1], %2;\n\t"  \
        "selp.b32 %0, 1, 0, p;\n\t}" : "=r"(_d) : "r"(_m), "r"(_p) : "memory");  \
    if (!_d) {                                                                   \
        asm volatile("{\n\t.reg .pred P1;\n\tWL_%=:\n\t"                         \
            "mbarrier.try_wait.parity.acquire.cta.shared::cta.b64 P1, [%0], %1, 0x989680;\n\t" \
            "@P1 bra.uni WD_%=;\n\tbra.uni WL_%=;\n\tWD_%=:\n\t}"                \
            :: "r"(_m), "r"(_p) : "memory");                                     \
    } } while (0)

// ---- packed-layout index helpers ----
__device__ __forceinline__ size_t act_off(int m, int k) {
    uint32_t byte = swz((uint32_t)((((m & 127) * 8) + ((k & 63) >> 3)) * 16)) + (k & 7) * 2;
    return ((size_t)((m >> 7) * 16 + (k >> 6))) * 8192 + (byte >> 1);
}
__device__ __forceinline__ size_t w_off(int n, int k) {
    uint32_t byte = (uint32_t)(((n >> 7) & 1) * 16384)
                  + swz((uint32_t)((((n & 127) * 8) + ((k & 63) >> 3)) * 16)) + (k & 7) * 2;
    return ((size_t)((n >> 8) * 16 + (k >> 6))) * 16384 + (byte >> 1);
}
__device__ __forceinline__ size_t qk_off(int bh, int s, int d) {
    uint32_t byte = swz((uint32_t)((((s & 127) * 8) + (d >> 3)) * 16)) + (d & 7) * 2;
    return ((size_t)(bh * 16 + (s >> 7))) * 8192 + (byte >> 1);
}
__device__ __forceinline__ size_t v_off(int bh, int s, int d) {
    uint32_t byte = (uint32_t)(((s & 127) >> 6) * 8192)
                  + swz((uint32_t)((d * 8 + ((s & 63) >> 3)) * 16)) + (s & 7) * 2;
    return ((size_t)(bh * 16 + (s >> 7))) * 8192 + (byte >> 1);
}

#if TC_OK
#define TCGEN05_ALLOC(sa, n) \
    asm volatile("tcgen05.alloc.cta_group::1.sync.aligned.shared::cta.b32 [%0], %1;" \
                 :: "r"((uint32_t)(sa)), "r"((uint32_t)(n)) : "memory")
#define TCGEN05_DEALLOC(t, n) \
    asm volatile("tcgen05.dealloc.cta_group::1.sync.aligned.b32 %0, %1;" :: "r"(t), "r"((uint32_t)(n)))
#define TCGEN05_RELINQ() \
    asm volatile("tcgen05.relinquish_alloc_permit.cta_group::1.sync.aligned;")
#define TCGEN05_COMMIT(mb) \
    asm volatile("tcgen05.commit.cta_group::1.mbarrier::arrive::one.shared::cluster.b64 [%0];" \
                 :: "r"((uint32_t)(mb)) : "memory")
#define TCGEN05_FENCE_AFTER()  asm volatile("tcgen05.fence::after_thread_sync;" ::: "memory")
#define TCGEN05_FENCE_BEFORE() asm volatile("tcgen05.fence::before_thread_sync;" ::: "memory")
#define TCGEN05_WAIT_LD()      asm volatile("tcgen05.wait::ld.sync.aligned;" ::: "memory")
#define TCGEN05_LD_X32(r, ta) \
    asm volatile("tcgen05.ld.sync.aligned.32x32b.x32.b32 " \
        "{%0,%1,%2,%3,%4,%5,%6,%7,%8,%9,%10,%11,%12,%13,%14,%15," \
        "%16,%17,%18,%19,%20,%21,%22,%23,%24,%25,%26,%27,%28,%29,%30,%31}, [%32];" \
        : "=r"((r)[0]),"=r"((r)[1]),"=r"((r)[2]),"=r"((r)[3]),"=r"((r)[4]),"=r"((r)[5]),"=r"((r)[6]),"=r"((r)[7]), \
          "=r"((r)[8]),"=r"((r)[9]),"=r"((r)[10]),"=r"((r)[11]),"=r"((r)[12]),"=r"((r)[13]),"=r"((r)[14]),"=r"((r)[15]), \
          "=r"((r)[16]),"=r"((r)[17]),"=r"((r)[18]),"=r"((r)[19]),"=r"((r)[20]),"=r"((r)[21]),"=r"((r)[22]),"=r"((r)[23]), \
          "=r"((r)[24]),"=r"((r)[25]),"=r"((r)[26]),"=r"((r)[27]),"=r"((r)[28]),"=r"((r)[29]),"=r"((r)[30]),"=r"((r)[31]) \
        : "r"(ta))

static __device__ __forceinline__ uint64_t make_desc_sw128(uint32_t base) {
    const uint64_t B = (uint64_t(2) << 61) | (uint64_t(1) << 46)
                     | (uint64_t(64) << 32) | (uint64_t(1) << 16);
    return B | ((uint64_t)(base >> 4) & 0x3FFF);
}
__device__ __forceinline__ void mma_f16_ss(uint32_t d, uint64_t a, uint64_t b,
                                           uint32_t idesc, uint32_t en) {
    asm volatile("{\n\t.reg .pred p;\n\tsetp.ne.u32 p, %5, 0;\n\t"
        "tcgen05.mma.cta_group::1.kind::f16 [%0], %1, %2, %3, {%4,%4,%4,%4}, p;\n\t}"
        :: "r"(d), "l"(a), "l"(b), "r"(idesc), "r"(0u), "r"(en) : "memory");
}
#endif // TC_OK

// ------------------------------ prep kernels -------------------------------
__global__ void split_kernel(const float* __restrict__ in,
                             bf16* __restrict__ hi, bf16* __restrict__ lo)
{
    int idx = blockIdx.x * blockDim.x + threadIdx.x;
    int m = idx >> 7, k = (idx & 127) * 8;
    float4 a = *(const float4*)&in[(size_t)m * DMODEL + k];
    float4 b = *(const float4*)&in[(size_t)m * DMODEL + k + 4];
    float f[8] = {a.x, a.y, a.z, a.w, b.x, b.y, b.z, b.w};
    uint32_t H[4], L[4];
#pragma unroll
    for (int e = 0; e < 4; e++) {
        uint32_t hh;
        asm("cvt.rn.bf16x2.f32 %0, %1, %2;" : "=r"(hh) : "f"(f[2*e+1]), "f"(f[2*e]));
        __nv_bfloat162 hv = *(__nv_bfloat162*)&hh;
        float r0 = f[2*e]   - __bfloat162float(hv.x);
        float r1 = f[2*e+1] - __bfloat162float(hv.y);
        uint32_t ll;
        asm("cvt.rn.bf16x2.f32 %0, %1, %2;" : "=r"(ll) : "f"(r1), "f"(r0));
        H[e] = hh; L[e] = ll;
    }
    size_t off = act_off(m, k);
    *(uint4*)&hi[off] = make_uint4(H[0], H[1], H[2], H[3]);
    *(uint4*)&lo[off] = make_uint4(L[0], L[1], L[2], L[3]);
}

// bias transpose-pack: in[q][k] -> g_bias2 tiles [qt][kt][k(128)][q(128)], *log2e
__global__ void btrans_kernel(const float* __restrict__ in)
{
    __shared__ float t[32][33];
    const int kb = blockIdx.x, qb = blockIdx.y;
    const int tx = threadIdx.x, ty = threadIdx.y;
#pragma unroll
    for (int i = 0; i < 4; i++)
        t[ty + i * 8][tx] = in[(size_t)(qb * 32 + ty + i * 8) * S_LEN + kb * 32 + tx] * LOG2E;
    __syncthreads();
    const size_t tb = ((size_t)((qb >> 2) * 16 + (kb >> 2))) * 16384;
#pragma unroll
    for (int i = 0; i < 4; i++) {
        const int k = kb * 32 + ty + i * 8;
        g_bias2[tb + (size_t)(k & 127) * 128 + (qb & 3) * 32 + tx] = t[tx][ty + i * 8];
    }
}

__global__ void wprep_kernel(const float* __restrict__ w0, const float* __restrict__ w1,
                             const float* __restrict__ w2, const float* __restrict__ w3)
{
    __shared__ float t[32][33];
    const float* W = (blockIdx.z == 0) ? w0 : (blockIdx.z == 1) ? w1
                   : (blockIdx.z == 2) ? w2 : w3;
    bf16* Whi = g_whi[blockIdx.z];
    bf16* Wlo = g_wlo[blockIdx.z];
    const int n0 = blockIdx.x * 32, k0 = blockIdx.y * 32;
    const int tx = threadIdx.x, ty = threadIdx.y;
#pragma unroll
    for (int i = 0; i < 4; i++)
        t[ty + i * 8][tx] = W[(size_t)(k0 + ty + i * 8) * DMODEL + n0 + tx];
    __syncthreads();
#pragma unroll
    for (int i = 0; i < 4; i++) {
        const int n = n0 + ty + i * 8, k = k0 + tx;
        float v = t[tx][ty + i * 8];
        bf16 h = __float2bfloat16_rn(v);
        size_t o = w_off(n, k);
        Whi[o] = h;
        Wlo[o] = __float2bfloat16_rn(v - __bfloat162float(h));
    }
}

// V transpose+split into packed V^T tiles (hi + lo)
__global__ __launch_bounds__(256)
void vtrans_kernel()
{
    __shared__ float t[64][65];
    const int bh = blockIdx.y, b = bh >> 4, h = bh & 15;
    const int s0 = blockIdx.x * 128;
    const int tid = threadIdx.x;
    for (int half = 0; half < 2; half++) {
        __syncthreads();
#pragma unroll
        for (int p = 0; p < 16; p++) {
            const int idx = tid + p * 256;
            const int d = idx & 63, sl = idx >> 6;
            t[d][sl] = g_v[(size_t)((s0 + half * 64 + sl) * 2 + b) * DMODEL + h * 64 + d];
        }
        __syncthreads();
#pragma unroll
        for (int p = 0; p < 8; p++) {
            const int idx = tid + p * 256;
            const int sp2 = idx & 31, d = idx >> 5;
            const int s = s0 + half * 64 + sp2 * 2;
            float v0 = t[d][sp2 * 2], v1 = t[d][sp2 * 2 + 1];
            __nv_bfloat162 H, L;
            H.x = __float2bfloat16_rn(v0);
            H.y = __float2bfloat16_rn(v1);
            L.x = __float2bfloat16_rn(v0 - __bfloat162float(H.x));
            L.y = __float2bfloat16_rn(v1 - __bfloat162float(H.y));
            const size_t o = v_off(bh, s, d);
            *(__nv_bfloat162*)&g_vthi[o] = H;
            *(__nv_bfloat162*)&g_vtlo[o] = L;
        }
    }
}

// --------------- tcgen05 GEMM (128x256, 2-stage, bulk-copy) ----------------
#define GTHREADS 512
#define GT_M 128
#define GT_N 256
#define GT_K 64
#define NCHUNK (DMODEL / GT_K)
#define OFF_AH 0
#define OFF_AL 16384
#define OFF_BH 32768
#define OFF_BL 65536
#define STAGE_B 98304
#define GEMM_SMEM (2 * STAGE_B + 1024)
#define GT_IDESC ((1u<<4)|(1u<<7)|(1u<<10)|(16u<<17)|(8u<<24))

__device__ __forceinline__ void gemm_core(
    const bf16* __restrict__ Ah, const bf16* __restrict__ Al,
    const bf16* __restrict__ Bh, const bf16* __restrict__ Bl,
    const float* __restrict__ bias, float* __restrict__ outf,
    bf16* __restrict__ outhi, bf16* __restrict__ outlo, int mode,
    char* dyn, uint32_t* s_tmem_p, uint64_t* s_mbar)
{
#if TC_OK
    const int tid = threadIdx.x, wid = tid >> 5, lid = tid & 31;
    const int n0 = blockIdx.x * GT_N, m0 = blockIdx.y * GT_M;
    const int mt = m0 >> 7, nt = n0 >> 8;

    uint32_t base = smem_u32(dyn);
    base = (base + 1023u) & ~1023u;
    const uint32_t full[2] = { smem_u32(&s_mbar[0]), smem_u32(&s_mbar[1]) };
    const uint32_t mmb[2]  = { smem_u32(&s_mbar[2]), smem_u32(&s_mbar[3]) };

    if (wid == 0) { TCGEN05_ALLOC(smem_u32(s_tmem_p), 256); TCGEN05_RELINQ(); }
    if (tid == 0) {
        MBARRIER_INIT(full[0], 1); MBARRIER_INIT(full[1], 1);
        MBARRIER_INIT(mmb[0], 1);  MBARRIER_INIT(mmb[1], 1);
    }
    __syncthreads();
    const uint32_t tmem = *s_tmem_p;

    if (tid == 0) {
#pragma unroll
        for (int c0 = 0; c0 < 2; c0++) {
            const uint32_t ss = base + c0 * STAGE_B;
            MBARRIER_EXPECT_TX(full[c0], (uint32_t)STAGE_B);
            bulkcp(ss + OFF_AH, Ah + (size_t)(mt * 16 + c0) * 8192,  16384, full[c0]);
            bulkcp(ss + OFF_AL, Al + (size_t)(mt * 16 + c0) * 8192,  16384, full[c0]);
            bulkcp(ss + OFF_BH, Bh + (size_t)(nt * 16 + c0) * 16384, 32768, full[c0]);
            bulkcp(ss + OFF_BL, Bl + (size_t)(nt * 16 + c0) * 16384, 32768, full[c0]);
        }
        int phF[2] = {0, 0}, phM[2] = {0, 0};
        for (int c = 0; c < NCHUNK; c++) {
            const int s = c & 1;
            const uint32_t ss = base + s * STAGE_B;
            MBAR_WAIT(full[s], phF[s]); phF[s] ^= 1;
            const uint64_t dAh = make_desc_sw128(ss + OFF_AH);
            const uint64_t dAl = make_desc_sw128(ss + OFF_AL);
#pragma unroll
            for (int sub = 0; sub < 2; sub++) {
                const uint64_t dBh = make_desc_sw128(ss + OFF_BH + sub * 16384);
                const uint64_t dBl = make_desc_sw128(ss + OFF_BL + sub * 16384);
                const uint32_t dst = tmem + sub * 128;
#pragma unroll
                for (int ks = 0; ks < 4; ks++)
                    mma_f16_ss(dst, dAh + ks * 2, dBh + ks * 2, GT_IDESC,
                               (c == 0 && ks == 0) ? 0u : 1u);
#pragma unroll
                for (int ks = 0; ks < 4; ks++)
                    mma_f16_ss(dst, dAh + ks * 2, dBl + ks * 2, GT_IDESC, 1u);
#pragma unroll
                for (int ks = 0; ks < 4; ks++)
                    mma_f16_ss(dst, dAl + ks * 2, dBh + ks * 2, GT_IDESC, 1u);
            }
            TCGEN05_COMMIT(mmb[s]);
            if (c + 2 < NCHUNK) {
                MBAR_WAIT(mmb[s], phM[s]); phM[s] ^= 1;
                MBARRIER_EXPECT_TX(full[s], (uint32_t)STAGE_B);
                bulkcp(ss + OFF_AH, Ah + (size_t)(mt * 16 + c + 2) * 8192,  16384, full[s]);
                bulkcp(ss + OFF_AL, Al + (size_t)(mt * 16 + c + 2) * 8192,  16384, full[s]);
                bulkcp(ss + OFF_BH, Bh + (size_t)(nt * 16 + c + 2) * 16384, 32768, full[s]);
                bulkcp(ss + OFF_BL, Bl + (size_t)(nt * 16 + c + 2) * 16384, 32768, full[s]);
            }
        }
        MBAR_WAIT(mmb[0], phM[0]);
        MBAR_WAIT(mmb[1], phM[1]);
    }
    __syncthreads();
    TCGEN05_FENCE_AFTER();

    {
        const int m = m0 + (wid & 3) * 32 + lid;
        const int s = m >> 1, b = m & 1;
#pragma unroll
        for (int gg = 0; gg < 2; gg++) {
            const int g = (wid >> 2) + gg * 4;
            uint32_t r[32];
            TCGEN05_LD_X32(r, tmem + g * 32);
            TCGEN05_WAIT_LD();
            const int cb = n0 + g * 32;
            if (mode == 0) {
#pragma unroll
                for (int q = 0; q < 8; q++) {
                    float4 v;
                    v.x = __uint_as_float(r[q * 4 + 0]) + bias[cb + q * 4 + 0];
                    v.y = __uint_as_float(r[q * 4 + 1]) + bias[cb + q * 4 + 1];
                    v.z = __uint_as_float(r[q * 4 + 2]) + bias[cb + q * 4 + 2];
                    v.w = __uint_as_float(r[q * 4 + 3]) + bias[cb + q * 4 + 3];
                    *(float4*)&outf[(size_t)m * DMODEL + cb + q * 4] = v;
                }
            } else {
                const int h = cb >> 6;
                const int bh = b * NHEADS + h;
#pragma unroll
                for (int q = 0; q < 16; q++) {
                    const int co = cb + q * 2;
                    float v0 = __uint_as_float(r[q * 2 + 0]) + bias[co + 0];
                    float v1 = __uint_as_float(r[q * 2 + 1]) + bias[co + 1];
                    __nv_bfloat162 H, L;
                    H.x = __float2bfloat16_rn(v0);
                    H.y = __float2bfloat16_rn(v1);
                    L.x = __float2bfloat16_rn(v0 - __bfloat162float(H.x));
                    L.y = __float2bfloat16_rn(v1 - __bfloat162float(H.y));
                    const size_t o = qk_off(bh, s, co & 63);
                    *(__nv_bfloat162*)&outhi[o] = H;
                    *(__nv_bfloat162*)&outlo[o] = L;
                }
            }
        }
        TCGEN05_FENCE_BEFORE();
    }
    __syncthreads();
    if (wid == 0) TCGEN05_DEALLOC(tmem, 256);
#else
    const int tid = threadIdx.x;
    const int n0 = blockIdx.x * GT_N, m0 = blockIdx.y * GT_M;
    for (int idx = tid; idx < GT_M * GT_N; idx += GTHREADS) {
        const int m = m0 + idx / GT_N, n = n0 + idx % GT_N;
        float sacc = bias[n];
        for (int k = 0; k < DMODEL; k++) {
            float a = __bfloat162float(Ah[act_off(m, k)]) +
                      __bfloat162float(Al[act_off(m, k)]);
            float bb = __bfloat162float(Bh[w_off(n, k)]) +
                       __bfloat162float(Bl[w_off(n, k)]);
            sacc = fmaf(a, bb, sacc);
        }
        if (mode == 0) outf[(size_t)m * DMODEL + n] = sacc;
        else {
            const int s = m >> 1, b = m & 1, h = n >> 6, d = n & 63;
            const size_t o = qk_off(b * NHEADS + h, s, d);
            bf16 hv = __float2bfloat16_rn(sacc);
            outhi[o] = hv;
            outlo[o] = __float2bfloat16_rn(sacc - __bfloat162float(hv));
        }
    }
#endif
}

__global__ __launch_bounds__(GTHREADS, 1)
void qkv_kernel(const float* __restrict__ bq, const float* __restrict__ bk,
                const float* __restrict__ bv)
{
    extern __shared__ char dyn[];
    __shared__ uint32_t s_tmem;
    __shared__ uint64_t s_mbar[4];
    const int z = blockIdx.z;
    if (z == 0)
        gemm_core(g_srchi, g_srclo, g_whi[0], g_wlo[0], bq, nullptr,
                  g_qhi, g_qlo, 1, dyn, &s_tmem, s_mbar);
    else if (z == 1)
        gemm_core(g_srchi, g_srclo, g_whi[1], g_wlo[1], bk, nullptr,
                  g_khi, g_klo, 1, dyn, &s_tmem, s_mbar);
    else
        gemm_core(g_srchi, g_srclo, g_whi[2], g_wlo[2], bv, g_v,
                  nullptr, nullptr, 0, dyn, &s_tmem, s_mbar);
}

__global__ __launch_bounds__(GTHREADS, 1)
void outproj_kernel(const float* __restrict__ bo, float* __restrict__ out)
{
    extern __shared__ char dyn[];
    __shared__ uint32_t s_tmem;
    __shared__ uint64_t s_mbar[4];
    gemm_core(g_atthi, g_attlo, g_whi[3], g_wlo[3], bo, out,
              nullptr, nullptr, 0, dyn, &s_tmem, s_mbar);
}

// --------------------------- tcgen05 attention -----------------------------
// TMEM: S0 @0-127, S1 @128-255, O @256-319.
// smem: Q hi/lo 32K | KV stage x2 (Kh,Kl,Vh,Vl = 64K each) | P hi/lo 64K
#define AQ_H  0
#define AQ_L  16384
#define AK(s) (32768 + (s) * 32768)
#define AV(s) (98304 + (s) * 32768)
#define AP    163840
#define ATTN_DYN (229376 + 1024)
#define IDESC_S  ((1u<<4)|(1u<<7)|(1u<<10)|(16u<<17)|(8u<<24))
#define IDESC_PV ((1u<<4)|(1u<<7)|(1u<<10)|(8u<<17)|(8u<<24))

__global__ __launch_bounds__(256, 1)
void attn_tc_kernel()
{
#if TC_OK
    extern __shared__ char dyn[];
    __shared__ uint32_t s_tmem;
    __shared__ uint64_t s_mb[4];   // mbS, mbP, fullKV0, fullKV1
    __shared__ float sm_red[2][128];

    const int tid = threadIdx.x, wid = tid >> 5, lid = tid & 31;
    const int g = wid >> 2;
    const int sp = wid & 3;
    const int row = sp * 32 + lid;
    const int bh = blockIdx.y;
    const int b = bh >> 4, h = bh & 15;
    const int q0 = blockIdx.x * 128;

    uint32_t base = smem_u32(dyn);
    base = (base + 1023u) & ~1023u;
    char* smp = dyn + (ptrdiff_t)(base - smem_u32(dyn));
    const uint32_t mbS = smem_u32(&s_mb[0]), mbP = smem_u32(&s_mb[1]);
    const uint32_t fullKV[2] = { smem_u32(&s_mb[2]), smem_u32(&s_mb[3]) };

    if (wid == 0) { TCGEN05_ALLOC(smem_u32(&s_tmem), 512); TCGEN05_RELINQ(); }
    if (tid == 0) {
        MBARRIER_INIT(mbS, 1); MBARRIER_INIT(mbP, 1);
        MBARRIER_INIT(fullKV[0], 1); MBARRIER_INIT(fullKV[1], 1);
    }
    __syncthreads();
    const uint32_t tmem = s_tmem;

    int phF0 = 0, phF1 = 0;
    // ---- prologue: Q + K0 + V0 via bulk, then S(0) ----
    if (tid == 0) {
        MBARRIER_EXPECT_TX(fullKV[0], 6 * 16384);
        bulkcp(base + AQ_H, g_qhi + (size_t)(bh * 16 + (q0 >> 7)) * 8192, 16384, fullKV[0]);
        bulkcp(base + AQ_L, g_qlo + (size_t)(bh * 16 + (q0 >> 7)) * 8192, 16384, fullKV[0]);
        bulkcp(base + AK(0),          g_khi  + (size_t)(bh * 16) * 8192, 16384, fullKV[0]);
        bulkcp(base + AK(0) + 16384,  g_klo  + (size_t)(bh * 16) * 8192, 16384, fullKV[0]);
        bulkcp(base + AV(0),          g_vthi + (size_t)(bh * 16) * 8192, 16384, fullKV[0]);
        bulkcp(base + AV(0) + 16384,  g_vtlo + (size_t)(bh * 16) * 8192, 16384, fullKV[0]);
        MBAR_WAIT(fullKV[0], 0); phF0 = 1;
        const uint64_t dQh = make_desc_sw128(base + AQ_H);
        const uint64_t dQl = make_desc_sw128(base + AQ_L);
        const uint64_t dKh = make_desc_sw128(base + AK(0));
        const uint64_t dKl = make_desc_sw128(base + AK(0) + 16384);
#pragma unroll
        for (int ks = 0; ks < 4; ks++) mma_f16_ss(tmem, dQh + ks*2, dKh + ks*2, IDESC_S, ks > 0);
#pragma unroll
        for (int ks = 0; ks < 4; ks++) mma_f16_ss(tmem, dQh + ks*2, dKl + ks*2, IDESC_S, 1);
#pragma unroll
        for (int ks = 0; ks < 4; ks++) mma_f16_ss(tmem, dQl + ks*2, dKh + ks*2, IDESC_S, 1);
        TCGEN05_COMMIT(mbS);
    }

    float l = 0.f;
    uint32_t phS = 0, phP = 0;

    for (int t = 0; t < 16; t++) {
        const int stg = t & 1;
        const int nst = (t + 1) & 1;

        // --- hoisted bias loads: coalesced LDG.32 from packed [k][q] tile ---
        float bz[64];
        {
            const float* bt = g_bias2
                + ((size_t)((q0 >> 7) * 16 + t)) * 16384 + row;
#pragma unroll
            for (int j = 0; j < 64; j++) bz[j] = bt[(size_t)(g * 64 + j) * 128];
        }

        // --- S(t) ready; read it ---
        MBAR_WAIT(mbS, phS); phS ^= 1;
        TCGEN05_FENCE_AFTER();
        float sv[64];
        {
            uint32_t r32a[32], r32b[32];
            TCGEN05_LD_X32(r32a, tmem + stg * 128 + g * 64);
            TCGEN05_LD_X32(r32b, tmem + stg * 128 + g * 64 + 32);
            TCGEN05_WAIT_LD();
#pragma unroll
            for (int i = 0; i < 32; i++) sv[i] = __uint_as_float(r32a[i]);
#pragma unroll
            for (int i = 0; i < 32; i++) sv[32 + i] = __uint_as_float(r32b[i]);
            TCGEN05_FENCE_BEFORE();
        }

        // --- PV(t-1) done -> V stage (t+1)&1 + P buffer free ---
        if (t > 0) { MBAR_WAIT(mbP, phP); phP ^= 1; TCGEN05_FENCE_AFTER(); }

        // --- prefetch KV(t+1): 4 bulk copies by tid0 ---
        if (t < 15 && tid == 0) {
            const size_t kt = (size_t)(bh * 16 + (t + 1));
            MBARRIER_EXPECT_TX(fullKV[nst], 4 * 16384);
            bulkcp(base + AK(nst),         g_khi  + kt * 8192, 16384, fullKV[nst]);
            bulkcp(base + AK(nst) + 16384, g_klo  + kt * 8192, 16384, fullKV[nst]);
            bulkcp(base + AV(nst),         g_vthi + kt * 8192, 16384, fullKV[nst]);
            bulkcp(base + AV(nst) + 16384, g_vtlo + kt * 8192, 16384, fullKV[nst]);
        }

        // --- P = ex2(sv*SCL + bias), sign gate, l accumulate ---
        float lsum = 0.f;
#pragma unroll
        for (int j = 0; j < 64; j++) {
            float pe = ex2_fast(fmaf(sv[j], SCL, bz[j]));
            lsum += pe;
            sv[j] = (bz[j] < 0.f) ? -pe : pe;
        }
        l += lsum;

        // --- write P (hi/lo, STS.128) ---
        {
            const int pco = AP + g * 16384;
#pragma unroll
            for (int jg = 0; jg < 8; jg++) {
                uint32_t H[4], L[4];
#pragma unroll
                for (int e = 0; e < 4; e++) {
                    float f0 = sv[jg * 8 + e * 2], f1 = sv[jg * 8 + e * 2 + 1];
                    uint32_t hh;
                    asm("cvt.rn.bf16x2.f32 %0, %1, %2;" : "=r"(hh) : "f"(f1), "f"(f0));
                    __nv_bfloat162 hv = *(__nv_bfloat162*)&hh;
                    float r0 = f0 - __bfloat162float(hv.x);
                    float r1 = f1 - __bfloat162float(hv.y);
                    uint32_t ll;
                    asm("cvt.rn.bf16x2.f32 %0, %1, %2;" : "=r"(ll) : "f"(r1), "f"(r0));
                    H[e] = hh; L[e] = ll;
                }
                const uint32_t off = swz((uint32_t)(row * 128 + jg * 16));
                *(uint4*)(smp + pco + off) = make_uint4(H[0], H[1], H[2], H[3]);
                *(uint4*)(smp + pco + 32768 + off) = make_uint4(L[0], L[1], L[2], L[3]);
            }
        }
        __syncthreads();   // P visible

        // --- S(t+1) first (after KV(t+1) arrives), then PV(t) ---
        if (tid == 0) {
            asm volatile("fence.proxy.async.shared::cta;" ::: "memory");
            TCGEN05_FENCE_AFTER();
            if (t < 15) {
                if (nst == 0) { MBAR_WAIT(fullKV[0], phF0); phF0 ^= 1; }
                else          { MBAR_WAIT(fullKV[1], phF1); phF1 ^= 1; }
                const uint64_t dQh = make_desc_sw128(base + AQ_H);
                const uint64_t dQl = make_desc_sw128(base + AQ_L);
                const uint64_t dKh = make_desc_sw128(base + AK(nst));
                const uint64_t dKl = make_desc_sw128(base + AK(nst) + 16384);
                const uint32_t sd = tmem + nst * 128;
#pragma unroll
                for (int ks = 0; ks < 4; ks++) mma_f16_ss(sd, dQh + ks*2, dKh + ks*2, IDESC_S, ks > 0);
#pragma unroll
                for (int ks = 0; ks < 4; ks++) mma_f16_ss(sd, dQh + ks*2, dKl + ks*2, IDESC_S, 1);
#pragma unroll
                for (int ks = 0; ks < 4; ks++) mma_f16_ss(sd, dQl + ks*2, dKh + ks*2, IDESC_S, 1);
                TCGEN05_COMMIT(mbS);
            }
            // PV(t): Ph*Vh + Ph*Vl + Pl*Vh
            const uint32_t vst = base + AV(stg);
#pragma unroll
            for (int c = 0; c < 2; c++) {
                const uint64_t dPh = make_desc_sw128(base + AP + c * 16384);
                const uint64_t dPl = make_desc_sw128(base + AP + 32768 + c * 16384);
                const uint64_t dVh = make_desc_sw128(vst + c * 8192);
                const uint64_t dVl = make_desc_sw128(vst + 16384 + c * 8192);
#pragma unroll
                for (int ks = 0; ks < 4; ks++)
                    mma_f16_ss(tmem + 256, dPh + ks*2, dVh + ks*2, IDESC_PV,
                               !(t == 0 && c == 0 && ks == 0));
#pragma unroll
                for (int ks = 0; ks < 4; ks++)
                    mma_f16_ss(tmem + 256, dPh + ks*2, dVl + ks*2, IDESC_PV, 1);
#pragma unroll
                for (int ks = 0; ks < 4; ks++)
                    mma_f16_ss(tmem + 256, dPl + ks*2, dVh + ks*2, IDESC_PV, 1);
            }
            TCGEN05_COMMIT(mbP);
        }
    }

    // --- final: O readback + l combine + packed write ---
    MBAR_WAIT(mbP, phP);
    TCGEN05_FENCE_AFTER();
    float O[32];
    {
        uint32_t r32[32];
        TCGEN05_LD_X32(r32, tmem + 256 + g * 32);
        TCGEN05_WAIT_LD();
#pragma unroll
        for (int i = 0; i < 32; i++) O[i] = __uint_as_float(r32[i]);
    }
    TCGEN05_FENCE_BEFORE();
    __syncthreads();
    sm_red[g][row] = l;
    __syncthreads();
    const float inv = 1.f / (l + sm_red[1 - g][row]);
    const int m = (q0 + row) * 2 + b;
#pragma unroll
    for (int i = 0; i < 16; i++) {
        const int kcol = h * 64 + g * 32 + 2 * i;
        float v0 = O[2 * i] * inv, v1 = O[2 * i + 1] * inv;
        __nv_bfloat162 H, L;
        H.x = __float2bfloat16_rn(v0);
        H.y = __float2bfloat16_rn(v1);
        L.x = __float2bfloat16_rn(v0 - __bfloat162float(H.x));
        L.y = __float2bfloat16_rn(v1 - __bfloat162float(H.y));
        const size_t o = act_off(m, kcol);
        *(__nv_bfloat162*)&g_atthi[o] = H;
        *(__nv_bfloat162*)&g_attlo[o] = L;
    }
    __syncthreads();
    if (wid == 0) TCGEN05_DEALLOC(tmem, 512);
#else
    // naive fallback (generic pass only; never executed on GB300)
    const int tid = threadIdx.x;
    if (tid >= 128) return;
    const int bh = blockIdx.y, b = bh >> 4, h = bh & 15;
    const int q = blockIdx.x * 128 + tid;
    float l = 0.f, O[64];
    for (int i = 0; i < 64; i++) O[i] = 0.f;
    for (int k = 0; k < S_LEN; k++) {
        float dot = 0.f;
        for (int d = 0; d < 64; d++) {
            float qv = __bfloat162float(g_qhi[qk_off(bh, q, d)]) +
                       __bfloat162float(g_qlo[qk_off(bh, q, d)]);
            float kv = __bfloat162float(g_khi[qk_off(bh, k, d)]) +
                       __bfloat162float(g_klo[qk_off(bh, k, d)]);
            dot = fmaf(qv, kv, dot);
        }
        float bzs = g_bias2[((size_t)((q >> 7) * 16 + (k >> 7))) * 16384
                            + (size_t)(k & 127) * 128 + (q & 127)];
        float e = exp2f(fmaf(dot, SCL, bzs));
        l += e;
        float pe = (bzs < 0.f) ? -e : e;
        for (int d = 0; d < 64; d++) {
            float vv = g_v[(size_t)(k * 2 + b) * DMODEL + h * 64 + d];
            O[d] = fmaf(pe, vv, O[d]);
        }
    }
    const int m = q * 2 + b;
    for (int d = 0; d < 64; d++) {
        float v = O[d] / l;
        bf16 hv = __float2bfloat16_rn(v);
        const size_t o = act_off(m, h * 64 + d);
        g_atthi[o] = hv;
        g_attlo[o] = __float2bfloat16_rn(v - __bfloat162float(hv));
    }
#endif
}

// ------------------------------ launch -------------------------------------
extern "C" void kernel_launch(void* const* d_in, const int* in_sizes, int n_in,
                              void* d_out, int out_size)
{
    const float* src    = (const float*)d_in[0];
    const float* bias2d = (const float*)d_in[1];
    const float* wq = (const float*)d_in[2];
    const float* bq = (const float*)d_in[3];
    const float* wk = (const float*)d_in[4];
    const float* bk = (const float*)d_in[5];
    const float* wv = (const float*)d_in[6];
    const float* bv = (const float*)d_in[7];
    const float* wo = (const float*)d_in[8];
    const float* bo = (const float*)d_in[9];
    float* out = (float*)d_out;

    cudaFuncSetAttribute(qkv_kernel,
                         cudaFuncAttributeMaxDynamicSharedMemorySize, GEMM_SMEM);
    cudaFuncSetAttribute(outproj_kernel,
                         cudaFuncAttributeMaxDynamicSharedMemorySize, GEMM_SMEM);
    cudaFuncSetAttribute(attn_tc_kernel,
                         cudaFuncAttributeMaxDynamicSharedMemorySize, ATTN_DYN);

    bf16 *srchi, *srclo;
    cudaGetSymbolAddress((void**)&srchi, g_srchi);
    cudaGetSymbolAddress((void**)&srclo, g_srclo);

    split_kernel<<<(M_ROWS * DMODEL / 8) / 256, 256>>>(src, srchi, srclo);
    btrans_kernel<<<dim3(S_LEN / 32, S_LEN / 32), dim3(32, 8)>>>(bias2d);
    wprep_kernel<<<dim3(32, 32, 4), dim3(32, 8)>>>(wq, wk, wv, wo);

    dim3 gg(DMODEL / GT_N, M_ROWS / GT_M, 3);
    qkv_kernel<<<gg, GTHREADS, GEMM_SMEM>>>(bq, bk, bv);

    vtrans_kernel<<<dim3(S_LEN / 128, NBH), 256>>>();

    attn_tc_kernel<<<dim3(S_LEN / 128, NBH), 256, ATTN_DYN>>>();

    dim3 go(DMODEL / GT_N, M_ROWS / GT_M);
    outproj_kernel<<<go, GTHREADS, GEMM_SMEM>>>(bo, out);
}